// round 15
// baseline (speedup 1.0000x reference)
#include <cuda_runtime.h>
#include <cuda_fp16.h>
#include <stdint.h>
#include <math.h>

#define NN 16000
#define EE 256000
#define EP (EE+NN)
#define DIN 1280
#define HD 256
#define GG 32
#define OO 64

// repacked-weight scratch layout (halves, transposed [n][K])
#define FPW_OFF   0
#define WL_OFF    327680
#define WR_OFF    458752
#define GINW_OFF  589824
#define RESW_OFF  720896
#define POOLW_OFF 851968
#define RW_TOT    917504

// dynamic smem for gemm: As[3][128][20] f32 + Bs[3][256][24] half
#define AS_STRIDE 2560              // floats per stage
#define BS_STRIDE 6144              // halves per stage (256*24)
#define AS_FLOATS (3*AS_STRIDE)
#define SMEM_SZ   (AS_FLOATS*4 + 3*BS_STRIDE*2)   // 30720 + 36864 = 67584

#define CSR_BLOCKS 148

// ---------------- device scratch (static, allocation-free) ----------------
__device__ float  d_h0[NN*HD];
__device__ float  d_h1[NN*HD];
__device__ float  d_xl[NN*HD];
__device__ float  d_xr[NN*HD];
__device__ __half d_rw[RW_TOT];
__device__ int    d_degGat[NN];
__device__ int    d_ptrGat[NN+1];
__device__ int    d_curGat[NN];
__device__ int    d_colGat[EP];
__device__ float  d_red[4];
__device__ float  d_gate[NN], d_gsum[GG], d_emb[GG*HD];
__device__ unsigned g_bar = 0;   // monotone ticket counter (never reset)

__device__ __forceinline__ void atomicMaxF(float* addr, float v){
  if (v >= 0.f) atomicMax((int*)addr, __float_as_int(v));
  else          atomicMin((unsigned int*)addr, __float_as_uint(v));
}

__device__ __forceinline__ uint32_t packh2(float2 v){
  uint32_t r; asm("cvt.rn.f16x2.f32 %0, %1, %2;" : "=r"(r) : "f"(v.y), "f"(v.x));
  return r;   // lo = v.x (lower k), hi = v.y
}

#define CP16(dst, src) asm volatile("cp.async.cg.shared.global [%0], [%1], 16;\n" :: "r"(dst), "l"(src))
#define CP_COMMIT()    asm volatile("cp.async.commit_group;\n" ::)
template<int N>
__device__ __forceinline__ void cp_wait(){ asm volatile("cp.async.wait_group %0;\n" :: "n"(N)); }

// grid-wide barrier: monotone ticket, all CSR_BLOCKS blocks co-resident.
__device__ __forceinline__ void gridbar(){
  __syncthreads();
  __threadfence();
  if (threadIdx.x == 0){
    unsigned t = atomicAdd(&g_bar, 1) + 1;
    unsigned target = ((t + CSR_BLOCKS - 1) / CSR_BLOCKS) * CSR_BLOCKS;
    for (;;){
      unsigned v;
      asm volatile("ld.global.cg.u32 %0, [%1];" : "=r"(v) : "l"(&g_bar));
      if (v >= target) break;
      __nanosleep(64);
    }
  }
  __syncthreads();
  __threadfence();
}

// ---- fused: init + weight repack (transpose + f16) + hist + scan ----
__global__ __launch_bounds__(1024)
void csr_kernel(const int* __restrict__ ei,
                int* degGat, int* indptr, int* cursor,
                float* red, float* emb, float* gate,
                float* out, const float* __restrict__ head_b2,
                const float* __restrict__ fpW, const float* __restrict__ wl,
                const float* __restrict__ wr, const float* __restrict__ ginw,
                const float* __restrict__ resw, const float* __restrict__ poolw,
                __half* __restrict__ rw){
  int gtid = blockIdx.x*blockDim.x + threadIdx.x;
  int gsz  = gridDim.x*blockDim.x;
  // phase 1: init + weight repack (dest-indexed: [n][K] f16)
  for (int i=gtid; i<NN; i+=gsz){ degGat[i]=0; gate[i]=0.f; }
  if (gtid < 4)  red[gtid]=0.f;
  for (int i=gtid; i<GG*HD; i+=gsz) emb[i]=0.f;
  for (int i=gtid; i<GG*OO; i+=gsz) out[i] = head_b2[i % OO];
  for (int idx=gtid; idx<RW_TOT; idx+=gsz){
    float v; int d = idx;
    if (d < 327680){                       // fpW: K=1280, N=256
      int n = d / 1280, k = d % 1280;
      v = fpW[k*256 + n];
    } else { d -= 327680;
      const float* src;
      if      (d < 131072) src = wl;
      else if (d < 262144){ src = wr;   d -= 131072; }
      else if (d < 393216){ src = ginw; d -= 262144; }
      else if (d < 524288){ src = resw; d -= 393216; }
      else                { src = poolw; d -= 524288; }
      int blk = d >> 16;                   // 0/1 (pool: always 0)
      int r = d & 65535;
      int n = r >> 8, k = r & 255;
      v = src[blk*65536 + k*256 + n];
    }
    rw[idx] = __float2half(v);
  }
  gridbar();
  // phase 2: histogram
  for (int e=gtid; e<EP; e+=gsz){
    int dnode = (e < EE) ? ei[EE+e] : (e-EE);
    atomicAdd(&degGat[dnode],1);
  }
  gridbar();
  // phase 3: scan (block 0 only)
  if (blockIdx.x == 0){
    int t = threadIdx.x;
    int lane = t & 31, wid = t >> 5;
    const int CH = 16;
    int st = t*CH;
    int dv[CH];
    int mySum = 0;
    #pragma unroll
    for (int i=0;i<CH;i++){
      int idx = st+i;
      dv[i] = (idx<NN)? degGat[idx] : 0;
      mySum += dv[i];
    }
    int inc = mySum;
    #pragma unroll
    for (int off=1; off<32; off<<=1){
      int n = __shfl_up_sync(0xffffffffu, inc, off);
      if (lane >= off) inc += n;
    }
    __shared__ int wtot[32];
    if (lane==31) wtot[wid] = inc;
    __syncthreads();
    if (wid==0){
      int v = wtot[lane];
      #pragma unroll
      for (int off=1; off<32; off<<=1){
        int n = __shfl_up_sync(0xffffffffu, v, off);
        if (lane >= off) v += n;
      }
      wtot[lane] = v;
    }
    __syncthreads();
    int run = inc - mySum + (wid>0 ? wtot[wid-1] : 0);
    #pragma unroll
    for (int i=0;i<CH;i++){
      int idx = st+i;
      if (idx<NN){ indptr[idx]=run; cursor[idx]=run; run+=dv[i]; }
    }
    if (t==1023) indptr[NN] = wtot[31];
  }
}

__global__ void fill_kernel(const int* __restrict__ ei, int* curGat, int* colGat){
  int e = blockIdx.x*blockDim.x+threadIdx.x;
  if (e >= EP) return;
  if (e < EE){
    colGat[atomicAdd(&curGat[ei[EE+e]],1)] = ei[e];
  } else {
    int v = e-EE;
    colGat[atomicAdd(&curGat[v],1)] = v;
  }
}

// --- 128x256-tile FP16 GEMM (fp32 accum), m16n8k16, 3-stage cp.async ---
// A: fp32 gmem -> f32 smem -> f16x2 pack at frag load.
// B: pre-repacked transposed [n][K] f16 (d_rw) -> half2 frag loads, no cvt.
enum { EPI_BIAS=0, EPI_RELU_BN=1, EPI_GIN=2, EPI_RES=3, EPI_POOL=4 };

template<int EPI, bool DUAL>
__global__ __launch_bounds__(256)
void gemm_tc(const float* __restrict__ A,
             const __half* __restrict__ B,  const float* __restrict__ bias,
             const __half* __restrict__ B2, const float* __restrict__ bias2, float* __restrict__ C2,
             const float* __restrict__ g,   const float* __restrict__ be,
             const float* __restrict__ lng, const float* __restrict__ lnb,
             const float* __restrict__ hres,
             const float* __restrict__ stats, float* __restrict__ statsOut,
             const float* __restrict__ W2pool, float* __restrict__ gatebuf,
             float* __restrict__ C, int K)
{
  extern __shared__ float sm[];
  float*  AsP = sm;
  __half* BsP = (__half*)(sm + AS_FLOATS);
  int tid = threadIdx.x;
  int lane = tid & 31, w = tid >> 5;
  int warpM = (w >> 2) * 64;
  int warpN = (w & 3) * 64;
  int m0 = blockIdx.x * 128;
  const __half* Bp = B; const float* biasp = bias; float* Cp = C;
  if (DUAL && blockIdx.y == 1){ Bp = B2; biasp = bias2; Cp = C2; }
  int tg = lane >> 2, tk = lane & 3;

  float acc[4][8][4];
  #pragma unroll
  for (int i=0;i<4;i++)
    #pragma unroll
    for (int j=0;j<8;j++)
      #pragma unroll
      for (int r=0;r<4;r++) acc[i][j][r]=0.f;

  int rowA  = tid >> 2;
  int k4A   = (tid & 3) * 4;

  uint32_t sA0[3], sA1[3], sB[3];
  #pragma unroll
  for (int s=0;s<3;s++){
    sA0[s] = (uint32_t)__cvta_generic_to_shared(&AsP[s*AS_STRIDE + rowA*20 + k4A]);
    sA1[s] = (uint32_t)__cvta_generic_to_shared(&AsP[s*AS_STRIDE + (rowA+64)*20 + k4A]);
    sB[s]  = (uint32_t)__cvta_generic_to_shared(&BsP[s*BS_STRIDE + tid*24]);
  }
  const float*  gA0 = A  + (long)(m0+rowA   )*K + k4A;
  const float*  gA1 = A  + (long)(m0+rowA+64)*K + k4A;
  const __half* gB  = Bp + (long)tid*K;     // row n = tid

  int nk = K >> 4;
  // prologue: stages 0 and 1
  CP16(sA0[0], gA0); CP16(sA1[0], gA1);
  CP16(sB[0],      gB);
  CP16(sB[0]+16,   gB+8);
  CP_COMMIT();
  if (nk > 1){
    CP16(sA0[1], gA0+16); CP16(sA1[1], gA1+16);
    CP16(sB[1],    gB+16);
    CP16(sB[1]+16, gB+24);
    CP_COMMIT();
  }

  int st = 0;
  for (int kt=0; kt<nk; kt++){
    if (kt+1 < nk) cp_wait<1>(); else cp_wait<0>();
    __syncthreads();
    if (kt+2 < nk){
      int s2 = st+2; if (s2>=3) s2-=3;
      int kb = (kt+2)<<4;
      CP16(sA0[s2], gA0+kb); CP16(sA1[s2], gA1+kb);
      CP16(sB[s2],    gB+kb);
      CP16(sB[s2]+16, gB+kb+8);
      CP_COMMIT();
    }
    const float*  Abase = AsP + st*AS_STRIDE;
    const __half* Bbase = BsP + st*BS_STRIDE;
    uint32_t a[4][4], b[8][2];
    #pragma unroll
    for (int i=0;i<4;i++){
      int r = warpM + i*16 + tg;
      float2 v0 = *(const float2*)&Abase[(r  )*20 + 2*tk];
      float2 v1 = *(const float2*)&Abase[(r+8)*20 + 2*tk];
      float2 v2 = *(const float2*)&Abase[(r  )*20 + 2*tk+8];
      float2 v3 = *(const float2*)&Abase[(r+8)*20 + 2*tk+8];
      a[i][0] = packh2(v0); a[i][1] = packh2(v1);
      a[i][2] = packh2(v2); a[i][3] = packh2(v3);
    }
    #pragma unroll
    for (int j=0;j<8;j++){
      int c = warpN + j*8 + tg;
      b[j][0] = *(const uint32_t*)&Bbase[c*24 + 2*tk];
      b[j][1] = *(const uint32_t*)&Bbase[c*24 + 2*tk + 8];
    }
    #pragma unroll
    for (int i=0;i<4;i++)
      #pragma unroll
      for (int j=0;j<8;j++)
        asm volatile("mma.sync.aligned.m16n8k16.row.col.f32.f16.f16.f32 "
          "{%0,%1,%2,%3}, {%4,%5,%6,%7}, {%8,%9}, {%0,%1,%2,%3};"
          : "+f"(acc[i][j][0]), "+f"(acc[i][j][1]),
            "+f"(acc[i][j][2]), "+f"(acc[i][j][3])
          : "r"(a[i][0]), "r"(a[i][1]), "r"(a[i][2]), "r"(a[i][3]),
            "r"(b[j][0]), "r"(b[j][1]));
    st++; if (st>=3) st-=3;
  }

  // ---- epilogue ----
  const float BNS = rsqrtf(1.0f + 1e-5f);
  float mean=0.f, rdenom=1.f;
  if (EPI==EPI_RES){
    const float inv = 1.0f/((float)NN*(float)HD);
    mean = stats[0]*inv;
    float var = stats[1]*inv - mean*mean;
    rdenom = 1.f/(sqrtf(fmaxf(var,0.f)) + 1e-5f);
  }
  float ssum=0.f, sq=0.f;
  float pgate[4][2];
  if (EPI==EPI_POOL){
    #pragma unroll
    for (int i=0;i<4;i++){ pgate[i][0]=0.f; pgate[i][1]=0.f; }
  }
  #pragma unroll
  for (int j=0;j<8;j++){
    int col = warpN + j*8 + tk*2;
    float b0 = biasp[col], b1 = biasp[col+1];
    float g0=0.f,g1=0.f,e0=0.f,e1=0.f;
    if (EPI==EPI_RELU_BN || EPI==EPI_GIN){
      g0=g[col]*BNS; g1=g[col+1]*BNS; e0=be[col]; e1=be[col+1];
    }
    float lg0=0.f,lg1=0.f,lb0=0.f,lb1=0.f;
    if (EPI==EPI_RES){
      lg0=lng[col]; lg1=lng[col+1]; lb0=lnb[col]; lb1=lnb[col+1];
    }
    float w20=0.f,w21=0.f;
    if (EPI==EPI_POOL){ w20=W2pool[col]; w21=W2pool[col+1]; }
    #pragma unroll
    for (int i=0;i<4;i++){
      #pragma unroll
      for (int h=0;h<2;h++){
        int row = m0 + warpM + i*16 + tg + h*8;
        float v0 = acc[i][j][h*2+0] + b0;
        float v1 = acc[i][j][h*2+1] + b1;
        if (EPI==EPI_RELU_BN){
          v0 = fmaxf(v0,0.f)*g0 + e0;
          v1 = fmaxf(v1,0.f)*g1 + e1;
        } else if (EPI==EPI_GIN){
          v0 = fmaxf(v0,0.f)*g0 + e0; v0 = (v0>0.f)? v0 : 0.2f*v0;
          v1 = fmaxf(v1,0.f)*g1 + e1; v1 = (v1>0.f)? v1 : 0.2f*v1;
          ssum += v0+v1; sq += v0*v0+v1*v1;
        } else if (EPI==EPI_RES){
          float2 hv = *(const float2*)&hres[(long)row*HD + col];
          v0 += (hv.x-mean)*rdenom*lg0 + lb0;
          v1 += (hv.y-mean)*rdenom*lg1 + lb1;
          v0 = (v0>0.f)? v0 : 0.2f*v0;
          v1 = (v1>0.f)? v1 : 0.2f*v1;
        } else if (EPI==EPI_POOL){
          pgate[i][h] += tanhf(v0)*w20 + tanhf(v1)*w21;
        }
        if (EPI!=EPI_POOL)
          *(float2*)&Cp[(long)row*HD + col] = make_float2(v0,v1);
      }
    }
  }
  if (EPI==EPI_GIN){
    #pragma unroll
    for (int off=16; off>0; off>>=1){
      ssum += __shfl_xor_sync(0xffffffffu, ssum, off);
      sq   += __shfl_xor_sync(0xffffffffu, sq,   off);
    }
    if (lane==0){
      atomicAdd(&statsOut[0], ssum);
      atomicAdd(&statsOut[1], sq);
    }
  }
  if (EPI==EPI_POOL){
    #pragma unroll
    for (int i=0;i<4;i++)
      #pragma unroll
      for (int h=0;h<2;h++){
        float p = pgate[i][h];
        p += __shfl_xor_sync(0xffffffffu, p, 1);
        p += __shfl_xor_sync(0xffffffffu, p, 2);
        if (tk==0){
          int row = m0 + warpM + i*16 + tg + h*8;
          atomicAdd(&gatebuf[row], p);
        }
      }
  }
}

// ------- GATv2: 4 warps/node = (edge-half x feature-half), float4 lanes -------
__global__ __launch_bounds__(256)
void gat_kernel(const float4* __restrict__ xl4, const float4* __restrict__ xr4,
                const int* __restrict__ indptr, const int* __restrict__ col,
                const float* __restrict__ att, const float* __restrict__ gbias,
                float* __restrict__ hout){
  __shared__ float part[2][2][32][5];
  int warpid = threadIdx.x >> 5;
  int lane = threadIdx.x & 31;
  int nib = warpid >> 2;
  int sub = warpid & 3;
  int eHalf = sub >> 1;
  int fHalf = sub & 1;
  int w = blockIdx.x*2 + nib;
  int fbase = fHalf*32 + lane;
  const float4* at4 = (const float4*)att;
  float4 a  = at4[fbase];
  float4 xr = xr4[w*64 + fbase];
  float4 acc = make_float4(0,0,0,0);
  float s = 0.f;
  int p0 = indptr[w], p1 = indptr[w+1];
  int mid = p0 + ((p1-p0)+1)/2;
  int jb = eHalf ? mid : p0;
  int je = eHalf ? p1  : mid;
  int j = jb;
  for (; j+1 < je; j += 2){
    int ua = col[j], ub = col[j+1];
    float4 xa = xl4[ua*64 + fbase];
    float4 xb = xl4[ub*64 + fbase];
    float qa, qb, v;
    v = xa.x+xr.x; v = fmaxf(v, 0.2f*v); qa  = v*a.x;
    v = xa.y+xr.y; v = fmaxf(v, 0.2f*v); qa += v*a.y;
    v = xa.z+xr.z; v = fmaxf(v, 0.2f*v); qa += v*a.z;
    v = xa.w+xr.w; v = fmaxf(v, 0.2f*v); qa += v*a.w;
    v = xb.x+xr.x; v = fmaxf(v, 0.2f*v); qb  = v*a.x;
    v = xb.y+xr.y; v = fmaxf(v, 0.2f*v); qb += v*a.y;
    v = xb.z+xr.z; v = fmaxf(v, 0.2f*v); qb += v*a.z;
    v = xb.w+xr.w; v = fmaxf(v, 0.2f*v); qb += v*a.w;
    qa += __shfl_xor_sync(0xffffffffu,qa,1);
    qb += __shfl_xor_sync(0xffffffffu,qb,1);
    qa += __shfl_xor_sync(0xffffffffu,qa,2);
    qb += __shfl_xor_sync(0xffffffffu,qb,2);
    qa += __shfl_xor_sync(0xffffffffu,qa,4);
    qb += __shfl_xor_sync(0xffffffffu,qb,4);
    float ca = __expf(qa), cb = __expf(qb);
    s += ca;
    acc.x += ca*xa.x; acc.y += ca*xa.y; acc.z += ca*xa.z; acc.w += ca*xa.w;
    s += cb;
    acc.x += cb*xb.x; acc.y += cb*xb.y; acc.z += cb*xb.z; acc.w += cb*xb.w;
  }
  if (j < je){
    int u = col[j];
    float4 x = xl4[u*64 + fbase];
    float q, v;
    v = x.x+xr.x; v = fmaxf(v, 0.2f*v); q  = v*a.x;
    v = x.y+xr.y; v = fmaxf(v, 0.2f*v); q += v*a.y;
    v = x.z+xr.z; v = fmaxf(v, 0.2f*v); q += v*a.z;
    v = x.w+xr.w; v = fmaxf(v, 0.2f*v); q += v*a.w;
    q += __shfl_xor_sync(0xffffffffu,q,1);
    q += __shfl_xor_sync(0xffffffffu,q,2);
    q += __shfl_xor_sync(0xffffffffu,q,4);
    float c = __expf(q);
    s += c;
    acc.x += c*x.x; acc.y += c*x.y; acc.z += c*x.z; acc.w += c*x.w;
  }
  if (eHalf == 1){
    part[nib][fHalf][lane][0] = acc.x;
    part[nib][fHalf][lane][1] = acc.y;
    part[nib][fHalf][lane][2] = acc.z;
    part[nib][fHalf][lane][3] = acc.w;
    part[nib][fHalf][lane][4] = s;
  }
  __syncthreads();
  if (eHalf == 0){
    acc.x += part[nib][fHalf][lane][0];
    acc.y += part[nib][fHalf][lane][1];
    acc.z += part[nib][fHalf][lane][2];
    acc.w += part[nib][fHalf][lane][3];
    s     += part[nib][fHalf][lane][4];
    float r = 1.f/(s+1e-16f);
    float4 b = ((const float4*)gbias)[fbase];
    float4 o;
    o.x = acc.x*r + b.x; o.y = acc.y*r + b.y;
    o.z = acc.z*r + b.z; o.w = acc.w*r + b.w;
    ((float4*)hout)[w*64 + fbase] = o;
  }
}

// ---- GIN aggregation via GAT CSR (self-loop in list), 4 warps/node ----
__global__ __launch_bounds__(256)
void ginagg_kernel(const float4* __restrict__ h4, const int* __restrict__ indptr,
                   const int* __restrict__ col, float* __restrict__ tmp){
  __shared__ float part[2][2][32][4];
  int warpid = threadIdx.x >> 5;
  int lane = threadIdx.x & 31;
  int nib = warpid >> 2;
  int sub = warpid & 3;
  int eHalf = sub >> 1;
  int fHalf = sub & 1;
  int w = blockIdx.x*2 + nib;
  int fbase = fHalf*32 + lane;
  float4 acc = make_float4(0,0,0,0);
  int p0 = indptr[w], p1 = indptr[w+1];
  int mid = p0 + ((p1-p0)+1)/2;
  int jb = eHalf ? mid : p0;
  int je = eHalf ? p1  : mid;
  int j = jb;
  for (; j+3 < je; j += 4){
    int u0 = col[j], u1 = col[j+1], u2 = col[j+2], u3 = col[j+3];
    float4 x0 = h4[u0*64 + fbase];
    float4 x1 = h4[u1*64 + fbase];
    float4 x2 = h4[u2*64 + fbase];
    float4 x3 = h4[u3*64 + fbase];
    acc.x+=x0.x; acc.y+=x0.y; acc.z+=x0.z; acc.w+=x0.w;
    acc.x+=x1.x; acc.y+=x1.y; acc.z+=x1.z; acc.w+=x1.w;
    acc.x+=x2.x; acc.y+=x2.y; acc.z+=x2.z; acc.w+=x2.w;
    acc.x+=x3.x; acc.y+=x3.y; acc.z+=x3.z; acc.w+=x3.w;
  }
  for (; j < je; j++){
    int u = col[j];
    float4 x = h4[u*64 + fbase];
    acc.x+=x.x; acc.y+=x.y; acc.z+=x.z; acc.w+=x.w;
  }
  if (eHalf == 1){
    part[nib][fHalf][lane][0]=acc.x;
    part[nib][fHalf][lane][1]=acc.y;
    part[nib][fHalf][lane][2]=acc.z;
    part[nib][fHalf][lane][3]=acc.w;
  }
  __syncthreads();
  if (eHalf == 0){
    acc.x+=part[nib][fHalf][lane][0];
    acc.y+=part[nib][fHalf][lane][1];
    acc.z+=part[nib][fHalf][lane][2];
    acc.w+=part[nib][fHalf][lane][3];
    ((float4*)tmp)[w*64 + fbase] = acc;
  }
}

// ---------------- pooling: batch softmax (single block) ----------------
__global__ void bsoftmax_kernel(float* __restrict__ gate, const int* __restrict__ batch,
                                const float* __restrict__ b2, float* __restrict__ gsum){
  __shared__ float smax[GG], ssum[GG];
  int t = threadIdx.x;  // 1024 threads
  if (t < GG){ smax[t] = -1e30f; ssum[t] = 0.f; }
  __syncthreads();
  float b2v = b2[0];
  for (int v=t; v<NN; v+=1024)
    atomicMaxF(&smax[batch[v]], gate[v]+b2v);
  __syncthreads();
  for (int v=t; v<NN; v+=1024){
    int b = batch[v];
    float e = __expf(gate[v]+b2v - smax[b]);
    gate[v] = e;
    atomicAdd(&ssum[b], e);
  }
  __syncthreads();
  if (t < GG) gsum[t] = ssum[t];
}

__global__ __launch_bounds__(256)
void emb_kernel(const float* __restrict__ gate, const int* __restrict__ batch,
                const float* __restrict__ gsum, const float* __restrict__ h, float* __restrict__ emb){
  int w = (blockIdx.x*blockDim.x + threadIdx.x)>>5;
  int lane = threadIdx.x & 31;
  if (w >= NN) return;
  int b = batch[w];
  float c = gate[w]/(gsum[b]+1e-16f);
  #pragma unroll
  for (int k=0;k<8;k++) atomicAdd(&emb[b*HD + k*32 + lane], c*h[w*HD + k*32 + lane]);
}

// ---------------- label heads: grid (OO,2), 128 thr, hidden-split ----------------
__global__ __launch_bounds__(128)
void head_kernel(const float* __restrict__ emb, const float* __restrict__ W1,
                 const float* __restrict__ b1, const float* __restrict__ g,
                 const float* __restrict__ be, const float* __restrict__ W2,
                 float* __restrict__ out){
  __shared__ float embS[GG*HD];
  __shared__ float sred[GG];
  int o = blockIdx.x;
  int half = blockIdx.y;
  int t = threadIdx.x;
  int hu = half*128 + t;
  for (int i=t;i<GG*HD;i+=128) embS[i]=emb[i];
  if (t < GG) sred[t]=0.f;
  __syncthreads();
  float acc[GG];
  #pragma unroll
  for (int b=0;b<GG;b++) acc[b]=0.f;
  const float* w = W1 + (long)o*HD*256 + hu;
  for (int d=0;d<HD;d++){
    float wv = w[(long)d*256];
    #pragma unroll
    for (int b=0;b<GG;b++) acc[b] += embS[b*HD+d]*wv;
  }
  const float BNS = rsqrtf(1.0f + 1e-5f);
  float bnscale = g[o*256+hu]*BNS;
  float beta = be[o*256+hu];
  float bb1 = b1[o*256+hu];
  float w2 = W2[o*256+hu];
  #pragma unroll
  for (int b=0;b<GG;b++){
    float z = acc[b]+bb1;
    float sv = z/(1.f+__expf(-z));
    float bnv = sv*bnscale + beta;
    atomicAdd(&sred[b], bnv*w2);
  }
  __syncthreads();
  if (t < GG) atomicAdd(&out[t*OO + o], sred[t]);
}

// ---------------- host launch ----------------
extern "C" void kernel_launch(void* const* d_in, const int* in_sizes, int n_in,
                              void* d_out, int out_size) {
  (void)in_sizes; (void)n_in; (void)out_size;
  const float* x      = (const float*)d_in[0];
  const int*   ei     = (const int*)  d_in[1];
  const int*   batch  = (const int*)  d_in[2];
  const float* fp_W   = (const float*)d_in[3];
  const float* fp_b   = (const float*)d_in[4];
  const float* fp_g   = (const float*)d_in[5];
  const float* fp_be  = (const float*)d_in[6];
  const float* gat_Wl = (const float*)d_in[7];
  const float* gat_bl = (const float*)d_in[8];
  const float* gat_Wr = (const float*)d_in[9];
  const float* gat_br = (const float*)d_in[10];
  const float* gat_att= (const float*)d_in[11];
  const float* gat_bias=(const float*)d_in[12];
  const float* gin_W  = (const float*)d_in[13];
  const float* gin_b  = (const float*)d_in[14];
  const float* gin_g  = (const float*)d_in[15];
  const float* gin_be = (const float*)d_in[16];
  const float* ln_g   = (const float*)d_in[17];
  const float* ln_b   = (const float*)d_in[18];
  const float* res_W  = (const float*)d_in[19];
  const float* res_b  = (const float*)d_in[20];
  const float* pool_W1= (const float*)d_in[21];
  const float* pool_b1= (const float*)d_in[22];
  const float* pool_W2= (const float*)d_in[23];
  const float* pool_b2= (const float*)d_in[24];
  const float* head_W1= (const float*)d_in[25];
  const float* head_b1= (const float*)d_in[26];
  const float* head_g = (const float*)d_in[27];
  const float* head_be= (const float*)d_in[28];
  const float* head_W2= (const float*)d_in[29];
  const float* head_b2= (const float*)d_in[30];

  float *h0,*h1,*xl,*xr,*red,*gate,*gsum,*emb;
  __half *rw;
  int *degGat,*ptrGat,*curGat,*colGat;
  cudaGetSymbolAddress((void**)&h0, d_h0);
  cudaGetSymbolAddress((void**)&h1, d_h1);
  cudaGetSymbolAddress((void**)&xl, d_xl);
  cudaGetSymbolAddress((void**)&xr, d_xr);
  cudaGetSymbolAddress((void**)&rw, d_rw);
  cudaGetSymbolAddress((void**)&red, d_red);
  cudaGetSymbolAddress((void**)&gate, d_gate);
  cudaGetSymbolAddress((void**)&gsum, d_gsum);
  cudaGetSymbolAddress((void**)&emb, d_emb);
  cudaGetSymbolAddress((void**)&degGat, d_degGat);
  cudaGetSymbolAddress((void**)&ptrGat, d_ptrGat);
  cudaGetSymbolAddress((void**)&curGat, d_curGat);
  cudaGetSymbolAddress((void**)&colGat, d_colGat);

  cudaFuncSetAttribute(gemm_tc<EPI_RELU_BN,false>, cudaFuncAttributeMaxDynamicSharedMemorySize, SMEM_SZ);
  cudaFuncSetAttribute(gemm_tc<EPI_BIAS,true>,     cudaFuncAttributeMaxDynamicSharedMemorySize, SMEM_SZ);
  cudaFuncSetAttribute(gemm_tc<EPI_GIN,false>,     cudaFuncAttributeMaxDynamicSharedMemorySize, SMEM_SZ);
  cudaFuncSetAttribute(gemm_tc<EPI_RES,false>,     cudaFuncAttributeMaxDynamicSharedMemorySize, SMEM_SZ);
  cudaFuncSetAttribute(gemm_tc<EPI_POOL,false>,    cudaFuncAttributeMaxDynamicSharedMemorySize, SMEM_SZ);

  dim3 gg1(NN/128, 1);
  dim3 gg2(NN/128, 2);

  // launch 1: init + f16 weight repack + hist + scan
  csr_kernel<<<CSR_BLOCKS, 1024>>>(ei, degGat, ptrGat, curGat,
                                   red, emb, gate, (float*)d_out, head_b2,
                                   fp_W, gat_Wl, gat_Wr, gin_W, res_W, pool_W1, rw);
  // launch 2: CSR fill
  fill_kernel<<<(EP+255)/256, 256>>>(ei, curGat, colGat);
  // launch 3: feature projection
  gemm_tc<EPI_RELU_BN,false><<<gg1,256,SMEM_SZ>>>(x, rw+FPW_OFF, fp_b, nullptr,nullptr,nullptr,
      fp_g, fp_be, nullptr,nullptr,nullptr,nullptr,nullptr,nullptr,nullptr, h0, DIN);

  float* cur = h0;
  float* alt = h1;
  for (int i=0;i<2;i++){
    const __half* Wl = rw + WL_OFF + (long)i*HD*HD;
    const float*  bl = gat_bl + (long)i*HD;
    const __half* Wr = rw + WR_OFF + (long)i*HD*HD;
    const float*  br = gat_br + (long)i*HD;
    const float*  at = gat_att + (long)i*8*32;
    const float*  gb = gat_bias + (long)i*HD;
    const __half* gW = rw + GINW_OFF + (long)i*HD*HD;
    const float*  gbi= gin_b + (long)i*HD;
    const float*  ggm= gin_g + (long)i*HD;
    const float*  gbe= gin_be + (long)i*HD;
    const float*  lg = ln_g + (long)i*HD;
    const float*  lb = ln_b + (long)i*HD;
    const __half* rW = rw + RESW_OFF + (long)i*HD*HD;
    const float*  rb = res_b + (long)i*HD;

    // launch 4 (i=0): dual GEMM  <-- ncu capture target
    gemm_tc<EPI_BIAS,true><<<gg2,256,SMEM_SZ>>>(cur, Wl, bl, Wr, br, xr,
        nullptr,nullptr,nullptr,nullptr,nullptr,nullptr,nullptr,nullptr,nullptr, xl, HD);
    gat_kernel<<<NN/2, 256>>>((const float4*)xl, (const float4*)xr, ptrGat, colGat, at, gb, alt);
    { float* t = cur; cur = alt; alt = t; }

    ginagg_kernel<<<NN/2, 256>>>((const float4*)cur, ptrGat, colGat, xl);
    gemm_tc<EPI_GIN,false><<<gg1,256,SMEM_SZ>>>(xl, gW, gbi, nullptr,nullptr,nullptr,
        ggm, gbe, nullptr,nullptr,nullptr,nullptr, red + 2*i, nullptr,nullptr, alt, HD);
    { float* t = cur; cur = alt; alt = t; }

    gemm_tc<EPI_RES,false><<<gg1,256,SMEM_SZ>>>(cur, rW, rb, nullptr,nullptr,nullptr,
        nullptr,nullptr, lg, lb, cur, red + 2*i, nullptr,nullptr,nullptr, alt, HD);
    { float* t = cur; cur = alt; alt = t; }
  }

  gemm_tc<EPI_POOL,false><<<gg1,256,SMEM_SZ>>>(cur, rw+POOLW_OFF, pool_b1, nullptr,nullptr,nullptr,
      nullptr,nullptr,nullptr,nullptr,nullptr,nullptr,nullptr, pool_W2, gate, nullptr, HD);
  bsoftmax_kernel<<<1, 1024>>>(gate, batch, pool_b2, gsum);
  emb_kernel<<<NN/8, 256>>>(gate, batch, gsum, cur, emb);

  head_kernel<<<dim3(OO,2), 128>>>(emb, head_W1, head_b1, head_g, head_be, head_W2, (float*)d_out);
}

// round 16
// speedup vs baseline: 1.1150x; 1.1150x over previous
#include <cuda_runtime.h>
#include <cuda_fp16.h>
#include <stdint.h>
#include <math.h>

#define NN 16000
#define EE 256000
#define EP (EE+NN)
#define DIN 1280
#define HD 256
#define GG 32
#define OO 64

// repacked-weight scratch layout (halves, transposed [n][K])
#define FPW_OFF   0
#define WL_OFF    327680
#define WR_OFF    458752
#define GINW_OFF  589824
#define RESW_OFF  720896
#define POOLW_OFF 851968
#define RW_TOT    917504

// dynamic smem: As[3][128][20] f32 + Bs[3][128][24] half
#define AS_STRIDE 2560              // floats per stage
#define BS_STRIDE 3072              // halves per stage (128*24)
#define AS_FLOATS (3*AS_STRIDE)
#define SMEM_SZ   (AS_FLOATS*4 + 3*BS_STRIDE*2)   // 30720 + 18432 = 49152

#define CSR_BLOCKS 148

// ---------------- device scratch (static, allocation-free) ----------------
__device__ float  d_h0[NN*HD];
__device__ float  d_h1[NN*HD];
__device__ float  d_xl[NN*HD];
__device__ float  d_xr[NN*HD];
__device__ __half d_rw[RW_TOT];
__device__ int    d_degGat[NN];
__device__ int    d_ptrGat[NN+1];
__device__ int    d_curGat[NN];
__device__ int    d_colGat[EP];
__device__ float  d_red[4];
__device__ float  d_gate[NN], d_gsum[GG], d_emb[GG*HD];
__device__ unsigned g_bar = 0;   // monotone ticket counter (never reset)

__device__ __forceinline__ void atomicMaxF(float* addr, float v){
  if (v >= 0.f) atomicMax((int*)addr, __float_as_int(v));
  else          atomicMin((unsigned int*)addr, __float_as_uint(v));
}

__device__ __forceinline__ uint32_t packh2(float2 v){
  uint32_t r; asm("cvt.rn.f16x2.f32 %0, %1, %2;" : "=r"(r) : "f"(v.y), "f"(v.x));
  return r;
}

#define CP16(dst, src) asm volatile("cp.async.cg.shared.global [%0], [%1], 16;\n" :: "r"(dst), "l"(src))
#define CP_COMMIT()    asm volatile("cp.async.commit_group;\n" ::)
template<int N>
__device__ __forceinline__ void cp_wait(){ asm volatile("cp.async.wait_group %0;\n" :: "n"(N)); }

__device__ __forceinline__ void gridbar(){
  __syncthreads();
  __threadfence();
  if (threadIdx.x == 0){
    unsigned t = atomicAdd(&g_bar, 1) + 1;
    unsigned target = ((t + CSR_BLOCKS - 1) / CSR_BLOCKS) * CSR_BLOCKS;
    for (;;){
      unsigned v;
      asm volatile("ld.global.cg.u32 %0, [%1];" : "=r"(v) : "l"(&g_bar));
      if (v >= target) break;
      __nanosleep(64);
    }
  }
  __syncthreads();
  __threadfence();
}

// ---- fused: init + weight repack (transpose + f16) + hist + scan ----
__global__ __launch_bounds__(1024)
void csr_kernel(const int* __restrict__ ei,
                int* degGat, int* indptr, int* cursor,
                float* red, float* emb, float* gate,
                float* out, const float* __restrict__ head_b2,
                const float* __restrict__ fpW, const float* __restrict__ wl,
                const float* __restrict__ wr, const float* __restrict__ ginw,
                const float* __restrict__ resw, const float* __restrict__ poolw,
                __half* __restrict__ rw){
  int gtid = blockIdx.x*blockDim.x + threadIdx.x;
  int gsz  = gridDim.x*blockDim.x;
  for (int i=gtid; i<NN; i+=gsz){ degGat[i]=0; gate[i]=0.f; }
  if (gtid < 4)  red[gtid]=0.f;
  for (int i=gtid; i<GG*HD; i+=gsz) emb[i]=0.f;
  for (int i=gtid; i<GG*OO; i+=gsz) out[i] = head_b2[i % OO];
  for (int idx=gtid; idx<RW_TOT; idx+=gsz){
    float v; int d = idx;
    if (d < 327680){
      int n = d / 1280, k = d % 1280;
      v = fpW[k*256 + n];
    } else { d -= 327680;
      const float* src;
      if      (d < 131072) src = wl;
      else if (d < 262144){ src = wr;   d -= 131072; }
      else if (d < 393216){ src = ginw; d -= 262144; }
      else if (d < 524288){ src = resw; d -= 393216; }
      else                { src = poolw; d -= 524288; }
      int blk = d >> 16;
      int r = d & 65535;
      int n = r >> 8, k = r & 255;
      v = src[blk*65536 + k*256 + n];
    }
    rw[idx] = __float2half(v);
  }
  gridbar();
  for (int e=gtid; e<EP; e+=gsz){
    int dnode = (e < EE) ? ei[EE+e] : (e-EE);
    atomicAdd(&degGat[dnode],1);
  }
  gridbar();
  if (blockIdx.x == 0){
    int t = threadIdx.x;
    int lane = t & 31, wid = t >> 5;
    const int CH = 16;
    int st = t*CH;
    int dv[CH];
    int mySum = 0;
    #pragma unroll
    for (int i=0;i<CH;i++){
      int idx = st+i;
      dv[i] = (idx<NN)? degGat[idx] : 0;
      mySum += dv[i];
    }
    int inc = mySum;
    #pragma unroll
    for (int off=1; off<32; off<<=1){
      int n = __shfl_up_sync(0xffffffffu, inc, off);
      if (lane >= off) inc += n;
    }
    __shared__ int wtot[32];
    if (lane==31) wtot[wid] = inc;
    __syncthreads();
    if (wid==0){
      int v = wtot[lane];
      #pragma unroll
      for (int off=1; off<32; off<<=1){
        int n = __shfl_up_sync(0xffffffffu, v, off);
        if (lane >= off) v += n;
      }
      wtot[lane] = v;
    }
    __syncthreads();
    int run = inc - mySum + (wid>0 ? wtot[wid-1] : 0);
    #pragma unroll
    for (int i=0;i<CH;i++){
      int idx = st+i;
      if (idx<NN){ indptr[idx]=run; cursor[idx]=run; run+=dv[i]; }
    }
    if (t==1023) indptr[NN] = wtot[31];
  }
}

__global__ void fill_kernel(const int* __restrict__ ei, int* curGat, int* colGat){
  int e = blockIdx.x*blockDim.x+threadIdx.x;
  if (e >= EP) return;
  if (e < EE){
    colGat[atomicAdd(&curGat[ei[EE+e]],1)] = ei[e];
  } else {
    int v = e-EE;
    colGat[atomicAdd(&curGat[v],1)] = v;
  }
}

// --- 128x128-tile FP16 GEMM (fp32 accum), m16n8k16, 3-stage, 2 CTA/SM ---
enum { EPI_BIAS=0, EPI_RELU_BN=1, EPI_GIN=2, EPI_RES=3, EPI_POOL=4 };

template<int EPI, bool DUAL>
__global__ __launch_bounds__(256,2)
void gemm_tc(const float* __restrict__ A,
             const __half* __restrict__ B,  const float* __restrict__ bias,
             const __half* __restrict__ B2, const float* __restrict__ bias2, float* __restrict__ C2,
             const float* __restrict__ g,   const float* __restrict__ be,
             const float* __restrict__ lng, const float* __restrict__ lnb,
             const float* __restrict__ hres,
             const float* __restrict__ stats, float* __restrict__ statsOut,
             const float* __restrict__ W2pool, float* __restrict__ gatebuf,
             float* __restrict__ C, int K)
{
  extern __shared__ float sm[];
  float*  AsP = sm;
  __half* BsP = (__half*)(sm + AS_FLOATS);
  int tid = threadIdx.x;
  int lane = tid & 31, w = tid >> 5;
  int warpM = (w & 3) * 32;
  int warpN = (w >> 2) * 64;
  int m0 = blockIdx.x * 128;
  const __half* Bp = B; const float* biasp = bias; float* Cp = C;
  int ny;
  if (DUAL){
    if (blockIdx.y >= 2){ Bp = B2; biasp = bias2; Cp = C2; }
    ny = blockIdx.y & 1;
  } else {
    ny = blockIdx.y;
  }
  int n0 = ny * 128;
  int tg = lane >> 2, tk = lane & 3;

  float acc[2][8][4];
  #pragma unroll
  for (int i=0;i<2;i++)
    #pragma unroll
    for (int j=0;j<8;j++)
      #pragma unroll
      for (int r=0;r<4;r++) acc[i][j][r]=0.f;

  int rowA  = tid >> 2;
  int k4A   = (tid & 3) * 4;
  int rowB  = tid >> 1;          // 0..127
  int koffB = (tid & 1) * 8;     // 0 or 8 halves

  uint32_t sA0[3], sA1[3], sB[3];
  #pragma unroll
  for (int s=0;s<3;s++){
    sA0[s] = (uint32_t)__cvta_generic_to_shared(&AsP[s*AS_STRIDE + rowA*20 + k4A]);
    sA1[s] = (uint32_t)__cvta_generic_to_shared(&AsP[s*AS_STRIDE + (rowA+64)*20 + k4A]);
    sB[s]  = (uint32_t)__cvta_generic_to_shared(&BsP[s*BS_STRIDE + rowB*24 + koffB]);
  }
  const float*  gA0 = A  + (long)(m0+rowA   )*K + k4A;
  const float*  gA1 = A  + (long)(m0+rowA+64)*K + k4A;
  const __half* gB  = Bp + (long)(n0+rowB)*K + koffB;

  int nk = K >> 4;
  CP16(sA0[0], gA0); CP16(sA1[0], gA1); CP16(sB[0], gB);
  CP_COMMIT();
  if (nk > 1){
    CP16(sA0[1], gA0+16); CP16(sA1[1], gA1+16); CP16(sB[1], gB+16);
    CP_COMMIT();
  }

  int st = 0;
  for (int kt=0; kt<nk; kt++){
    if (kt+1 < nk) cp_wait<1>(); else cp_wait<0>();
    __syncthreads();
    if (kt+2 < nk){
      int s2 = st+2; if (s2>=3) s2-=3;
      int kb = (kt+2)<<4;
      CP16(sA0[s2], gA0+kb); CP16(sA1[s2], gA1+kb); CP16(sB[s2], gB+kb);
      CP_COMMIT();
    }
    const float*  Abase = AsP + st*AS_STRIDE;
    const __half* Bbase = BsP + st*BS_STRIDE;
    uint32_t a[2][4], b[8][2];
    #pragma unroll
    for (int i=0;i<2;i++){
      int r = warpM + i*16 + tg;
      float2 v0 = *(const float2*)&Abase[(r  )*20 + 2*tk];
      float2 v1 = *(const float2*)&Abase[(r+8)*20 + 2*tk];
      float2 v2 = *(const float2*)&Abase[(r  )*20 + 2*tk+8];
      float2 v3 = *(const float2*)&Abase[(r+8)*20 + 2*tk+8];
      a[i][0] = packh2(v0); a[i][1] = packh2(v1);
      a[i][2] = packh2(v2); a[i][3] = packh2(v3);
    }
    #pragma unroll
    for (int j=0;j<8;j++){
      int c = warpN + j*8 + tg;
      b[j][0] = *(const uint32_t*)&Bbase[c*24 + 2*tk];
      b[j][1] = *(const uint32_t*)&Bbase[c*24 + 2*tk + 8];
    }
    #pragma unroll
    for (int i=0;i<2;i++)
      #pragma unroll
      for (int j=0;j<8;j++)
        asm volatile("mma.sync.aligned.m16n8k16.row.col.f32.f16.f16.f32 "
          "{%0,%1,%2,%3}, {%4,%5,%6,%7}, {%8,%9}, {%0,%1,%2,%3};"
          : "+f"(acc[i][j][0]), "+f"(acc[i][j][1]),
            "+f"(acc[i][j][2]), "+f"(acc[i][j][3])
          : "r"(a[i][0]), "r"(a[i][1]), "r"(a[i][2]), "r"(a[i][3]),
            "r"(b[j][0]), "r"(b[j][1]));
    st++; if (st>=3) st-=3;
  }

  // ---- epilogue ----
  const float BNS = rsqrtf(1.0f + 1e-5f);
  float mean=0.f, rdenom=1.f;
  if (EPI==EPI_RES){
    const float inv = 1.0f/((float)NN*(float)HD);
    mean = stats[0]*inv;
    float var = stats[1]*inv - mean*mean;
    rdenom = 1.f/(sqrtf(fmaxf(var,0.f)) + 1e-5f);
  }
  float ssum=0.f, sq=0.f;
  float pgate[2][2];
  if (EPI==EPI_POOL){
    pgate[0][0]=pgate[0][1]=pgate[1][0]=pgate[1][1]=0.f;
  }
  #pragma unroll
  for (int j=0;j<8;j++){
    int col = n0 + warpN + j*8 + tk*2;
    float b0 = biasp[col], b1 = biasp[col+1];
    float g0=0.f,g1=0.f,e0=0.f,e1=0.f;
    if (EPI==EPI_RELU_BN || EPI==EPI_GIN){
      g0=g[col]*BNS; g1=g[col+1]*BNS; e0=be[col]; e1=be[col+1];
    }
    float lg0=0.f,lg1=0.f,lb0=0.f,lb1=0.f;
    if (EPI==EPI_RES){
      lg0=lng[col]; lg1=lng[col+1]; lb0=lnb[col]; lb1=lnb[col+1];
    }
    float w20=0.f,w21=0.f;
    if (EPI==EPI_POOL){ w20=W2pool[col]; w21=W2pool[col+1]; }
    #pragma unroll
    for (int i=0;i<2;i++){
      #pragma unroll
      for (int h=0;h<2;h++){
        int row = m0 + warpM + i*16 + tg + h*8;
        float v0 = acc[i][j][h*2+0] + b0;
        float v1 = acc[i][j][h*2+1] + b1;
        if (EPI==EPI_RELU_BN){
          v0 = fmaxf(v0,0.f)*g0 + e0;
          v1 = fmaxf(v1,0.f)*g1 + e1;
        } else if (EPI==EPI_GIN){
          v0 = fmaxf(v0,0.f)*g0 + e0; v0 = (v0>0.f)? v0 : 0.2f*v0;
          v1 = fmaxf(v1,0.f)*g1 + e1; v1 = (v1>0.f)? v1 : 0.2f*v1;
          ssum += v0+v1; sq += v0*v0+v1*v1;
        } else if (EPI==EPI_RES){
          float2 hv = *(const float2*)&hres[(long)row*HD + col];
          v0 += (hv.x-mean)*rdenom*lg0 + lb0;
          v1 += (hv.y-mean)*rdenom*lg1 + lb1;
          v0 = (v0>0.f)? v0 : 0.2f*v0;
          v1 = (v1>0.f)? v1 : 0.2f*v1;
        } else if (EPI==EPI_POOL){
          pgate[i][h] += tanhf(v0)*w20 + tanhf(v1)*w21;
        }
        if (EPI!=EPI_POOL)
          *(float2*)&Cp[(long)row*HD + col] = make_float2(v0,v1);
      }
    }
  }
  if (EPI==EPI_GIN){
    #pragma unroll
    for (int off=16; off>0; off>>=1){
      ssum += __shfl_xor_sync(0xffffffffu, ssum, off);
      sq   += __shfl_xor_sync(0xffffffffu, sq,   off);
    }
    if (lane==0){
      atomicAdd(&statsOut[0], ssum);
      atomicAdd(&statsOut[1], sq);
    }
  }
  if (EPI==EPI_POOL){
    #pragma unroll
    for (int i=0;i<2;i++)
      #pragma unroll
      for (int h=0;h<2;h++){
        float p = pgate[i][h];
        p += __shfl_xor_sync(0xffffffffu, p, 1);
        p += __shfl_xor_sync(0xffffffffu, p, 2);
        if (tk==0){
          int row = m0 + warpM + i*16 + tg + h*8;
          atomicAdd(&gatebuf[row], p);
        }
      }
  }
}

// ------- GATv2: 4 warps/node = (edge-half x feature-half), float4 lanes -------
__global__ __launch_bounds__(256)
void gat_kernel(const float4* __restrict__ xl4, const float4* __restrict__ xr4,
                const int* __restrict__ indptr, const int* __restrict__ col,
                const float* __restrict__ att, const float* __restrict__ gbias,
                float* __restrict__ hout){
  __shared__ float part[2][2][32][5];
  int warpid = threadIdx.x >> 5;
  int lane = threadIdx.x & 31;
  int nib = warpid >> 2;
  int sub = warpid & 3;
  int eHalf = sub >> 1;
  int fHalf = sub & 1;
  int w = blockIdx.x*2 + nib;
  int fbase = fHalf*32 + lane;
  const float4* at4 = (const float4*)att;
  float4 a  = at4[fbase];
  float4 xr = xr4[w*64 + fbase];
  float4 acc = make_float4(0,0,0,0);
  float s = 0.f;
  int p0 = indptr[w], p1 = indptr[w+1];
  int mid = p0 + ((p1-p0)+1)/2;
  int jb = eHalf ? mid : p0;
  int je = eHalf ? p1  : mid;
  int j = jb;
  for (; j+1 < je; j += 2){
    int ua = col[j], ub = col[j+1];
    float4 xa = xl4[ua*64 + fbase];
    float4 xb = xl4[ub*64 + fbase];
    float qa, qb, v;
    v = xa.x+xr.x; v = fmaxf(v, 0.2f*v); qa  = v*a.x;
    v = xa.y+xr.y; v = fmaxf(v, 0.2f*v); qa += v*a.y;
    v = xa.z+xr.z; v = fmaxf(v, 0.2f*v); qa += v*a.z;
    v = xa.w+xr.w; v = fmaxf(v, 0.2f*v); qa += v*a.w;
    v = xb.x+xr.x; v = fmaxf(v, 0.2f*v); qb  = v*a.x;
    v = xb.y+xr.y; v = fmaxf(v, 0.2f*v); qb += v*a.y;
    v = xb.z+xr.z; v = fmaxf(v, 0.2f*v); qb += v*a.z;
    v = xb.w+xr.w; v = fmaxf(v, 0.2f*v); qb += v*a.w;
    qa += __shfl_xor_sync(0xffffffffu,qa,1);
    qb += __shfl_xor_sync(0xffffffffu,qb,1);
    qa += __shfl_xor_sync(0xffffffffu,qa,2);
    qb += __shfl_xor_sync(0xffffffffu,qb,2);
    qa += __shfl_xor_sync(0xffffffffu,qa,4);
    qb += __shfl_xor_sync(0xffffffffu,qb,4);
    float ca = __expf(qa), cb = __expf(qb);
    s += ca;
    acc.x += ca*xa.x; acc.y += ca*xa.y; acc.z += ca*xa.z; acc.w += ca*xa.w;
    s += cb;
    acc.x += cb*xb.x; acc.y += cb*xb.y; acc.z += cb*xb.z; acc.w += cb*xb.w;
  }
  if (j < je){
    int u = col[j];
    float4 x = xl4[u*64 + fbase];
    float q, v;
    v = x.x+xr.x; v = fmaxf(v, 0.2f*v); q  = v*a.x;
    v = x.y+xr.y; v = fmaxf(v, 0.2f*v); q += v*a.y;
    v = x.z+xr.z; v = fmaxf(v, 0.2f*v); q += v*a.z;
    v = x.w+xr.w; v = fmaxf(v, 0.2f*v); q += v*a.w;
    q += __shfl_xor_sync(0xffffffffu,q,1);
    q += __shfl_xor_sync(0xffffffffu,q,2);
    q += __shfl_xor_sync(0xffffffffu,q,4);
    float c = __expf(q);
    s += c;
    acc.x += c*x.x; acc.y += c*x.y; acc.z += c*x.z; acc.w += c*x.w;
  }
  if (eHalf == 1){
    part[nib][fHalf][lane][0] = acc.x;
    part[nib][fHalf][lane][1] = acc.y;
    part[nib][fHalf][lane][2] = acc.z;
    part[nib][fHalf][lane][3] = acc.w;
    part[nib][fHalf][lane][4] = s;
  }
  __syncthreads();
  if (eHalf == 0){
    acc.x += part[nib][fHalf][lane][0];
    acc.y += part[nib][fHalf][lane][1];
    acc.z += part[nib][fHalf][lane][2];
    acc.w += part[nib][fHalf][lane][3];
    s     += part[nib][fHalf][lane][4];
    float r = 1.f/(s+1e-16f);
    float4 b = ((const float4*)gbias)[fbase];
    float4 o;
    o.x = acc.x*r + b.x; o.y = acc.y*r + b.y;
    o.z = acc.z*r + b.z; o.w = acc.w*r + b.w;
    ((float4*)hout)[w*64 + fbase] = o;
  }
}

// ---- GIN aggregation via GAT CSR (self-loop in list), 4 warps/node ----
__global__ __launch_bounds__(256)
void ginagg_kernel(const float4* __restrict__ h4, const int* __restrict__ indptr,
                   const int* __restrict__ col, float* __restrict__ tmp){
  __shared__ float part[2][2][32][4];
  int warpid = threadIdx.x >> 5;
  int lane = threadIdx.x & 31;
  int nib = warpid >> 2;
  int sub = warpid & 3;
  int eHalf = sub >> 1;
  int fHalf = sub & 1;
  int w = blockIdx.x*2 + nib;
  int fbase = fHalf*32 + lane;
  float4 acc = make_float4(0,0,0,0);
  int p0 = indptr[w], p1 = indptr[w+1];
  int mid = p0 + ((p1-p0)+1)/2;
  int jb = eHalf ? mid : p0;
  int je = eHalf ? p1  : mid;
  int j = jb;
  for (; j+3 < je; j += 4){
    int u0 = col[j], u1 = col[j+1], u2 = col[j+2], u3 = col[j+3];
    float4 x0 = h4[u0*64 + fbase];
    float4 x1 = h4[u1*64 + fbase];
    float4 x2 = h4[u2*64 + fbase];
    float4 x3 = h4[u3*64 + fbase];
    acc.x+=x0.x; acc.y+=x0.y; acc.z+=x0.z; acc.w+=x0.w;
    acc.x+=x1.x; acc.y+=x1.y; acc.z+=x1.z; acc.w+=x1.w;
    acc.x+=x2.x; acc.y+=x2.y; acc.z+=x2.z; acc.w+=x2.w;
    acc.x+=x3.x; acc.y+=x3.y; acc.z+=x3.z; acc.w+=x3.w;
  }
  for (; j < je; j++){
    int u = col[j];
    float4 x = h4[u*64 + fbase];
    acc.x+=x.x; acc.y+=x.y; acc.z+=x.z; acc.w+=x.w;
  }
  if (eHalf == 1){
    part[nib][fHalf][lane][0]=acc.x;
    part[nib][fHalf][lane][1]=acc.y;
    part[nib][fHalf][lane][2]=acc.z;
    part[nib][fHalf][lane][3]=acc.w;
  }
  __syncthreads();
  if (eHalf == 0){
    acc.x+=part[nib][fHalf][lane][0];
    acc.y+=part[nib][fHalf][lane][1];
    acc.z+=part[nib][fHalf][lane][2];
    acc.w+=part[nib][fHalf][lane][3];
    ((float4*)tmp)[w*64 + fbase] = acc;
  }
}

// ---- pooling: batch softmax, warp-segmented (batch is sorted) ----
__global__ void bsoftmax_kernel(float* __restrict__ gate, const int* __restrict__ batch,
                                const float* __restrict__ b2, float* __restrict__ gsum){
  __shared__ float smax[GG], ssum[GG];
  int t = threadIdx.x;  // 1024 threads
  int lane = t & 31, wid = t >> 5;
  if (t < GG){ smax[t] = -1e30f; ssum[t] = 0.f; }
  __syncthreads();
  float b2v = b2[0];
  // pass 1: max (warp handles contiguous 32-chunk)
  for (int base = wid*32; base < NN; base += 1024){
    int v = base + lane;
    bool ok = v < NN;
    int b = ok ? batch[v] : -1;
    float gv = ok ? gate[v]+b2v : -1e30f;
    int b0 = __shfl_sync(0xffffffffu, b, 0);
    if (__all_sync(0xffffffffu, b==b0 || !ok)){
      float m = gv;
      m = fmaxf(m, __shfl_xor_sync(0xffffffffu, m, 16));
      m = fmaxf(m, __shfl_xor_sync(0xffffffffu, m, 8));
      m = fmaxf(m, __shfl_xor_sync(0xffffffffu, m, 4));
      m = fmaxf(m, __shfl_xor_sync(0xffffffffu, m, 2));
      m = fmaxf(m, __shfl_xor_sync(0xffffffffu, m, 1));
      if (lane==0) atomicMaxF(&smax[b0], m);
    } else if (ok){
      atomicMaxF(&smax[b], gv);
    }
  }
  __syncthreads();
  // pass 2: exp + sum
  for (int base = wid*32; base < NN; base += 1024){
    int v = base + lane;
    bool ok = v < NN;
    int b = ok ? batch[v] : -1;
    float e = 0.f;
    if (ok){
      e = __expf(gate[v]+b2v - smax[b]);
      gate[v] = e;
    }
    int b0 = __shfl_sync(0xffffffffu, b, 0);
    if (__all_sync(0xffffffffu, b==b0 || !ok)){
      float sum = e;
      sum += __shfl_xor_sync(0xffffffffu, sum, 16);
      sum += __shfl_xor_sync(0xffffffffu, sum, 8);
      sum += __shfl_xor_sync(0xffffffffu, sum, 4);
      sum += __shfl_xor_sync(0xffffffffu, sum, 2);
      sum += __shfl_xor_sync(0xffffffffu, sum, 1);
      if (lane==0) atomicAdd(&ssum[b0], sum);
    } else if (ok){
      atomicAdd(&ssum[b], e);
    }
  }
  __syncthreads();
  if (t < GG) gsum[t] = ssum[t];
}

__global__ __launch_bounds__(256)
void emb_kernel(const float* __restrict__ gate, const int* __restrict__ batch,
                const float* __restrict__ gsum, const float* __restrict__ h, float* __restrict__ emb){
  int w = (blockIdx.x*blockDim.x + threadIdx.x)>>5;
  int lane = threadIdx.x & 31;
  if (w >= NN) return;
  int b = batch[w];
  float c = gate[w]/(gsum[b]+1e-16f);
  #pragma unroll
  for (int k=0;k<8;k++) atomicAdd(&emb[b*HD + k*32 + lane], c*h[w*HD + k*32 + lane]);
}

// ---------------- label heads: grid (OO,2), 128 thr, hidden-split ----------------
__global__ __launch_bounds__(128)
void head_kernel(const float* __restrict__ emb, const float* __restrict__ W1,
                 const float* __restrict__ b1, const float* __restrict__ g,
                 const float* __restrict__ be, const float* __restrict__ W2,
                 float* __restrict__ out){
  __shared__ float embS[GG*HD];
  __shared__ float sred[GG];
  int o = blockIdx.x;
  int half = blockIdx.y;
  int t = threadIdx.x;
  int hu = half*128 + t;
  for (int i=t;i<GG*HD;i+=128) embS[i]=emb[i];
  if (t < GG) sred[t]=0.f;
  __syncthreads();
  float acc[GG];
  #pragma unroll
  for (int b=0;b<GG;b++) acc[b]=0.f;
  const float* w = W1 + (long)o*HD*256 + hu;
  for (int d=0;d<HD;d++){
    float wv = w[(long)d*256];
    #pragma unroll
    for (int b=0;b<GG;b++) acc[b] += embS[b*HD+d]*wv;
  }
  const float BNS = rsqrtf(1.0f + 1e-5f);
  float bnscale = g[o*256+hu]*BNS;
  float beta = be[o*256+hu];
  float bb1 = b1[o*256+hu];
  float w2 = W2[o*256+hu];
  #pragma unroll
  for (int b=0;b<GG;b++){
    float z = acc[b]+bb1;
    float sv = z/(1.f+__expf(-z));
    float bnv = sv*bnscale + beta;
    atomicAdd(&sred[b], bnv*w2);
  }
  __syncthreads();
  if (t < GG) atomicAdd(&out[t*OO + o], sred[t]);
}

// ---------------- host launch ----------------
extern "C" void kernel_launch(void* const* d_in, const int* in_sizes, int n_in,
                              void* d_out, int out_size) {
  (void)in_sizes; (void)n_in; (void)out_size;
  const float* x      = (const float*)d_in[0];
  const int*   ei     = (const int*)  d_in[1];
  const int*   batch  = (const int*)  d_in[2];
  const float* fp_W   = (const float*)d_in[3];
  const float* fp_b   = (const float*)d_in[4];
  const float* fp_g   = (const float*)d_in[5];
  const float* fp_be  = (const float*)d_in[6];
  const float* gat_Wl = (const float*)d_in[7];
  const float* gat_bl = (const float*)d_in[8];
  const float* gat_Wr = (const float*)d_in[9];
  const float* gat_br = (const float*)d_in[10];
  const float* gat_att= (const float*)d_in[11];
  const float* gat_bias=(const float*)d_in[12];
  const float* gin_W  = (const float*)d_in[13];
  const float* gin_b  = (const float*)d_in[14];
  const float* gin_g  = (const float*)d_in[15];
  const float* gin_be = (const float*)d_in[16];
  const float* ln_g   = (const float*)d_in[17];
  const float* ln_b   = (const float*)d_in[18];
  const float* res_W  = (const float*)d_in[19];
  const float* res_b  = (const float*)d_in[20];
  const float* pool_W1= (const float*)d_in[21];
  const float* pool_b1= (const float*)d_in[22];
  const float* pool_W2= (const float*)d_in[23];
  const float* pool_b2= (const float*)d_in[24];
  const float* head_W1= (const float*)d_in[25];
  const float* head_b1= (const float*)d_in[26];
  const float* head_g = (const float*)d_in[27];
  const float* head_be= (const float*)d_in[28];
  const float* head_W2= (const float*)d_in[29];
  const float* head_b2= (const float*)d_in[30];

  float *h0,*h1,*xl,*xr,*red,*gate,*gsum,*emb;
  __half *rw;
  int *degGat,*ptrGat,*curGat,*colGat;
  cudaGetSymbolAddress((void**)&h0, d_h0);
  cudaGetSymbolAddress((void**)&h1, d_h1);
  cudaGetSymbolAddress((void**)&xl, d_xl);
  cudaGetSymbolAddress((void**)&xr, d_xr);
  cudaGetSymbolAddress((void**)&rw, d_rw);
  cudaGetSymbolAddress((void**)&red, d_red);
  cudaGetSymbolAddress((void**)&gate, d_gate);
  cudaGetSymbolAddress((void**)&gsum, d_gsum);
  cudaGetSymbolAddress((void**)&emb, d_emb);
  cudaGetSymbolAddress((void**)&degGat, d_degGat);
  cudaGetSymbolAddress((void**)&ptrGat, d_ptrGat);
  cudaGetSymbolAddress((void**)&curGat, d_curGat);
  cudaGetSymbolAddress((void**)&colGat, d_colGat);

  cudaFuncSetAttribute(gemm_tc<EPI_RELU_BN,false>, cudaFuncAttributeMaxDynamicSharedMemorySize, SMEM_SZ);
  cudaFuncSetAttribute(gemm_tc<EPI_BIAS,true>,     cudaFuncAttributeMaxDynamicSharedMemorySize, SMEM_SZ);
  cudaFuncSetAttribute(gemm_tc<EPI_GIN,false>,     cudaFuncAttributeMaxDynamicSharedMemorySize, SMEM_SZ);
  cudaFuncSetAttribute(gemm_tc<EPI_RES,false>,     cudaFuncAttributeMaxDynamicSharedMemorySize, SMEM_SZ);
  cudaFuncSetAttribute(gemm_tc<EPI_POOL,false>,    cudaFuncAttributeMaxDynamicSharedMemorySize, SMEM_SZ);

  dim3 gg1(NN/128, 2);   // (125,2): two N-halves
  dim3 gg2(NN/128, 4);   // dual: y = wset*2 + nhalf

  // launch 1: init + f16 weight repack + hist + scan
  csr_kernel<<<CSR_BLOCKS, 1024>>>(ei, degGat, ptrGat, curGat,
                                   red, emb, gate, (float*)d_out, head_b2,
                                   fp_W, gat_Wl, gat_Wr, gin_W, res_W, pool_W1, rw);
  // launch 2: CSR fill
  fill_kernel<<<(EP+255)/256, 256>>>(ei, curGat, colGat);
  // launch 3: feature projection
  gemm_tc<EPI_RELU_BN,false><<<gg1,256,SMEM_SZ>>>(x, rw+FPW_OFF, fp_b, nullptr,nullptr,nullptr,
      fp_g, fp_be, nullptr,nullptr,nullptr,nullptr,nullptr,nullptr,nullptr, h0, DIN);

  float* cur = h0;
  float* alt = h1;
  for (int i=0;i<2;i++){
    const __half* Wl = rw + WL_OFF + (long)i*HD*HD;
    const float*  bl = gat_bl + (long)i*HD;
    const __half* Wr = rw + WR_OFF + (long)i*HD*HD;
    const float*  br = gat_br + (long)i*HD;
    const float*  at = gat_att + (long)i*8*32;
    const float*  gb = gat_bias + (long)i*HD;
    const __half* gW = rw + GINW_OFF + (long)i*HD*HD;
    const float*  gbi= gin_b + (long)i*HD;
    const float*  ggm= gin_g + (long)i*HD;
    const float*  gbe= gin_be + (long)i*HD;
    const float*  lg = ln_g + (long)i*HD;
    const float*  lb = ln_b + (long)i*HD;
    const __half* rW = rw + RESW_OFF + (long)i*HD*HD;
    const float*  rb = res_b + (long)i*HD;

    // launch 4 (i=0): dual GEMM  <-- ncu capture target (expect occ ~25%, ~25us)
    gemm_tc<EPI_BIAS,true><<<gg2,256,SMEM_SZ>>>(cur, Wl, bl, Wr, br, xr,
        nullptr,nullptr,nullptr,nullptr,nullptr,nullptr,nullptr,nullptr,nullptr, xl, HD);
    gat_kernel<<<NN/2, 256>>>((const float4*)xl, (const float4*)xr, ptrGat, colGat, at, gb, alt);
    { float* t = cur; cur = alt; alt = t; }

    ginagg_kernel<<<NN/2, 256>>>((const float4*)cur, ptrGat, colGat, xl);
    gemm_tc<EPI_GIN,false><<<gg1,256,SMEM_SZ>>>(xl, gW, gbi, nullptr,nullptr,nullptr,
        ggm, gbe, nullptr,nullptr,nullptr,nullptr, red + 2*i, nullptr,nullptr, alt, HD);
    { float* t = cur; cur = alt; alt = t; }

    gemm_tc<EPI_RES,false><<<gg1,256,SMEM_SZ>>>(cur, rW, rb, nullptr,nullptr,nullptr,
        nullptr,nullptr, lg, lb, cur, red + 2*i, nullptr,nullptr,nullptr, alt, HD);
    { float* t = cur; cur = alt; alt = t; }
  }

  gemm_tc<EPI_POOL,false><<<gg1,256,SMEM_SZ>>>(cur, rw+POOLW_OFF, pool_b1, nullptr,nullptr,nullptr,
      nullptr,nullptr,nullptr,nullptr,nullptr,nullptr,nullptr, pool_W2, gate, nullptr, HD);
  bsoftmax_kernel<<<1, 1024>>>(gate, batch, pool_b2, gsum);
  emb_kernel<<<NN/8, 256>>>(gate, batch, gsum, cur, emb);

  head_kernel<<<dim3(OO,2), 128>>>(emb, head_W1, head_b1, head_g, head_be, head_W2, (float*)d_out);
}

// round 17
// speedup vs baseline: 1.1249x; 1.0088x over previous
#include <cuda_runtime.h>
#include <cuda_fp16.h>
#include <stdint.h>
#include <math.h>

#define NN 16000
#define EE 256000
#define EP (EE+NN)
#define DIN 1280
#define HD 256
#define GG 32
#define OO 64

// repacked-weight scratch layout (halves, transposed [n][K])
#define FPW_OFF   0
#define WL_OFF    327680
#define WR_OFF    458752
#define GINW_OFF  589824
#define RESW_OFF  720896
#define POOLW_OFF 851968
#define RW_TOT    917504

// dynamic smem: max( As[3][128][20] f32 + Bs[3][128][24] half ,  Ah[3][128][24] half + Bs ... )
#define AS_STRIDE 2560              // floats per stage (fp32 A path)
#define AH_STRIDE 3072              // halves per stage (f16 A path, 128*24)
#define BS_STRIDE 3072              // halves per stage (128*24)
#define AS_FLOATS (3*AS_STRIDE)
#define SMEM_SZ   (AS_FLOATS*4 + 3*BS_STRIDE*2)   // 30720 + 18432 = 49152 (covers both paths)

#define CSR_BLOCKS 148

// ---------------- device scratch (static, allocation-free) ----------------
__device__ float  d_h0[NN*HD];
__device__ float  d_h1[NN*HD];
__device__ float  d_xl[NN*HD];
__device__ float  d_xr[NN*HD];
__device__ __half d_xh[(long)NN*DIN];
__device__ __half d_rw[RW_TOT];
__device__ int    d_degGat[NN];
__device__ int    d_ptrGat[NN+1];
__device__ int    d_curGat[NN];
__device__ int    d_colGat[EP];
__device__ float  d_red[4];
__device__ float  d_gate[NN], d_gsum[GG], d_emb[GG*HD];
__device__ unsigned g_bar = 0;   // monotone ticket counter (never reset)

__device__ __forceinline__ void atomicMaxF(float* addr, float v){
  if (v >= 0.f) atomicMax((int*)addr, __float_as_int(v));
  else          atomicMin((unsigned int*)addr, __float_as_uint(v));
}

__device__ __forceinline__ uint32_t packh2(float2 v){
  uint32_t r; asm("cvt.rn.f16x2.f32 %0, %1, %2;" : "=r"(r) : "f"(v.y), "f"(v.x));
  return r;
}

#define CP16(dst, src) asm volatile("cp.async.cg.shared.global [%0], [%1], 16;\n" :: "r"(dst), "l"(src))
#define CP_COMMIT()    asm volatile("cp.async.commit_group;\n" ::)
template<int N>
__device__ __forceinline__ void cp_wait(){ asm volatile("cp.async.wait_group %0;\n" :: "n"(N)); }

__device__ __forceinline__ void gridbar(){
  __syncthreads();
  __threadfence();
  if (threadIdx.x == 0){
    unsigned t = atomicAdd(&g_bar, 1) + 1;
    unsigned target = ((t + CSR_BLOCKS - 1) / CSR_BLOCKS) * CSR_BLOCKS;
    for (;;){
      unsigned v;
      asm volatile("ld.global.cg.u32 %0, [%1];" : "=r"(v) : "l"(&g_bar));
      if (v >= target) break;
      __nanosleep(64);
    }
  }
  __syncthreads();
  __threadfence();
}

// ---- fused: init + x->f16 + weight repack + hist + scan ----
__global__ __launch_bounds__(1024)
void csr_kernel(const int* __restrict__ ei, const float* __restrict__ x,
                int* degGat, int* indptr, int* cursor,
                float* red, float* emb, float* gate,
                float* out, const float* __restrict__ head_b2,
                const float* __restrict__ fpW, const float* __restrict__ wl,
                const float* __restrict__ wr, const float* __restrict__ ginw,
                const float* __restrict__ resw, const float* __restrict__ poolw,
                __half* __restrict__ xh, __half* __restrict__ rw){
  int gtid = blockIdx.x*blockDim.x + threadIdx.x;
  int gsz  = gridDim.x*blockDim.x;
  for (int i=gtid; i<NN; i+=gsz){ degGat[i]=0; gate[i]=0.f; }
  if (gtid < 4)  red[gtid]=0.f;
  for (int i=gtid; i<GG*HD; i+=gsz) emb[i]=0.f;
  for (int i=gtid; i<GG*OO; i+=gsz) out[i] = head_b2[i % OO];
  // x -> f16 (rn, identical to packh2 rounding in the GEMM)
  {
    const float4* x4 = (const float4*)x;
    const int n4 = (NN*DIN)/4;
    for (int i=gtid; i<n4; i+=gsz){
      float4 v = x4[i];
      __half2 lo = __floats2half2_rn(v.x, v.y);
      __half2 hi = __floats2half2_rn(v.z, v.w);
      ((__half2*)xh)[i*2]   = lo;
      ((__half2*)xh)[i*2+1] = hi;
    }
  }
  for (int idx=gtid; idx<RW_TOT; idx+=gsz){
    float v; int d = idx;
    if (d < 327680){
      int n = d / 1280, k = d % 1280;
      v = fpW[k*256 + n];
    } else { d -= 327680;
      const float* src;
      if      (d < 131072) src = wl;
      else if (d < 262144){ src = wr;   d -= 131072; }
      else if (d < 393216){ src = ginw; d -= 262144; }
      else if (d < 524288){ src = resw; d -= 393216; }
      else                { src = poolw; d -= 524288; }
      int blk = d >> 16;
      int r = d & 65535;
      int n = r >> 8, k = r & 255;
      v = src[blk*65536 + k*256 + n];
    }
    rw[idx] = __float2half(v);
  }
  gridbar();
  for (int e=gtid; e<EP; e+=gsz){
    int dnode = (e < EE) ? ei[EE+e] : (e-EE);
    atomicAdd(&degGat[dnode],1);
  }
  gridbar();
  if (blockIdx.x == 0){
    int t = threadIdx.x;
    int lane = t & 31, wid = t >> 5;
    const int CH = 16;
    int st = t*CH;
    int dv[CH];
    int mySum = 0;
    #pragma unroll
    for (int i=0;i<CH;i++){
      int idx = st+i;
      dv[i] = (idx<NN)? degGat[idx] : 0;
      mySum += dv[i];
    }
    int inc = mySum;
    #pragma unroll
    for (int off=1; off<32; off<<=1){
      int n = __shfl_up_sync(0xffffffffu, inc, off);
      if (lane >= off) inc += n;
    }
    __shared__ int wtot[32];
    if (lane==31) wtot[wid] = inc;
    __syncthreads();
    if (wid==0){
      int v = wtot[lane];
      #pragma unroll
      for (int off=1; off<32; off<<=1){
        int n = __shfl_up_sync(0xffffffffu, v, off);
        if (lane >= off) v += n;
      }
      wtot[lane] = v;
    }
    __syncthreads();
    int run = inc - mySum + (wid>0 ? wtot[wid-1] : 0);
    #pragma unroll
    for (int i=0;i<CH;i++){
      int idx = st+i;
      if (idx<NN){ indptr[idx]=run; cursor[idx]=run; run+=dv[i]; }
    }
    if (t==1023) indptr[NN] = wtot[31];
  }
}

__global__ void fill_kernel(const int* __restrict__ ei, int* curGat, int* colGat){
  int e = blockIdx.x*blockDim.x+threadIdx.x;
  if (e >= EP) return;
  if (e < EE){
    colGat[atomicAdd(&curGat[ei[EE+e]],1)] = ei[e];
  } else {
    int v = e-EE;
    colGat[atomicAdd(&curGat[v],1)] = v;
  }
}

// --- 128x128-tile FP16 GEMM (fp32 accum), m16n8k16, 3-stage, 2 CTA/SM ---
// AHALF=false: A fp32 gmem -> f32 smem -> packh2 at frag load.
// AHALF=true:  A f16 gmem (pre-rounded) -> f16 smem -> bare u32 frag loads.
enum { EPI_BIAS=0, EPI_RELU_BN=1, EPI_GIN=2, EPI_RES=3, EPI_POOL=4 };

template<int EPI, bool DUAL, bool AHALF>
__global__ __launch_bounds__(256,2)
void gemm_tc(const void* __restrict__ Av,
             const __half* __restrict__ B,  const float* __restrict__ bias,
             const __half* __restrict__ B2, const float* __restrict__ bias2, float* __restrict__ C2,
             const float* __restrict__ g,   const float* __restrict__ be,
             const float* __restrict__ lng, const float* __restrict__ lnb,
             const float* __restrict__ hres,
             const float* __restrict__ stats, float* __restrict__ statsOut,
             const float* __restrict__ W2pool, float* __restrict__ gatebuf,
             float* __restrict__ C, int K)
{
  extern __shared__ float sm[];
  float*  AsP = sm;                                  // fp32 A path
  __half* AhP = (__half*)sm;                         // f16 A path
  __half* BsP = AHALF ? ((__half*)sm + 3*AH_STRIDE)
                      : (__half*)(sm + AS_FLOATS);
  int tid = threadIdx.x;
  int lane = tid & 31, w = tid >> 5;
  int warpM = (w & 3) * 32;
  int warpN = (w >> 2) * 64;
  int m0 = blockIdx.x * 128;
  const __half* Bp = B; const float* biasp = bias; float* Cp = C;
  int ny;
  if (DUAL){
    if (blockIdx.y >= 2){ Bp = B2; biasp = bias2; Cp = C2; }
    ny = blockIdx.y & 1;
  } else {
    ny = blockIdx.y;
  }
  int n0 = ny * 128;
  int tg = lane >> 2, tk = lane & 3;

  float acc[2][8][4];
  #pragma unroll
  for (int i=0;i<2;i++)
    #pragma unroll
    for (int j=0;j<8;j++)
      #pragma unroll
      for (int r=0;r<4;r++) acc[i][j][r]=0.f;

  int rowA  = tid >> 2;
  int k4A   = (tid & 3) * 4;
  int rowB  = tid >> 1;          // 0..127
  int koffB = (tid & 1) * 8;     // 0 or 8 halves

  uint32_t sA0[3], sA1[3], sB[3];
  #pragma unroll
  for (int s=0;s<3;s++){
    if (AHALF){
      sA0[s] = (uint32_t)__cvta_generic_to_shared(&AhP[s*AH_STRIDE + rowB*24 + koffB]);
      sA1[s] = 0;
    } else {
      sA0[s] = (uint32_t)__cvta_generic_to_shared(&AsP[s*AS_STRIDE + rowA*20 + k4A]);
      sA1[s] = (uint32_t)__cvta_generic_to_shared(&AsP[s*AS_STRIDE + (rowA+64)*20 + k4A]);
    }
    sB[s]  = (uint32_t)__cvta_generic_to_shared(&BsP[s*BS_STRIDE + rowB*24 + koffB]);
  }
  const float*  gA0 = AHALF ? nullptr : (const float*)Av + (long)(m0+rowA   )*K + k4A;
  const float*  gA1 = AHALF ? nullptr : (const float*)Av + (long)(m0+rowA+64)*K + k4A;
  const __half* gAh = AHALF ? (const __half*)Av + (long)(m0+rowB)*K + koffB : nullptr;
  const __half* gB  = Bp + (long)(n0+rowB)*K + koffB;

  int nk = K >> 4;
  if (AHALF){ CP16(sA0[0], gAh); } else { CP16(sA0[0], gA0); CP16(sA1[0], gA1); }
  CP16(sB[0], gB);
  CP_COMMIT();
  if (nk > 1){
    if (AHALF){ CP16(sA0[1], gAh+16); } else { CP16(sA0[1], gA0+16); CP16(sA1[1], gA1+16); }
    CP16(sB[1], gB+16);
    CP_COMMIT();
  }

  int st = 0;
  for (int kt=0; kt<nk; kt++){
    if (kt+1 < nk) cp_wait<1>(); else cp_wait<0>();
    __syncthreads();
    if (kt+2 < nk){
      int s2 = st+2; if (s2>=3) s2-=3;
      int kb = (kt+2)<<4;
      if (AHALF){ CP16(sA0[s2], gAh+kb); } else { CP16(sA0[s2], gA0+kb); CP16(sA1[s2], gA1+kb); }
      CP16(sB[s2], gB+kb);
      CP_COMMIT();
    }
    const __half* Bbase = BsP + st*BS_STRIDE;
    uint32_t a[2][4], b[8][2];
    if (AHALF){
      const __half* Abase = AhP + st*AH_STRIDE;
      #pragma unroll
      for (int i=0;i<2;i++){
        int r = warpM + i*16 + tg;
        a[i][0] = *(const uint32_t*)&Abase[(r  )*24 + 2*tk];
        a[i][1] = *(const uint32_t*)&Abase[(r+8)*24 + 2*tk];
        a[i][2] = *(const uint32_t*)&Abase[(r  )*24 + 2*tk+8];
        a[i][3] = *(const uint32_t*)&Abase[(r+8)*24 + 2*tk+8];
      }
    } else {
      const float* Abase = AsP + st*AS_STRIDE;
      #pragma unroll
      for (int i=0;i<2;i++){
        int r = warpM + i*16 + tg;
        float2 v0 = *(const float2*)&Abase[(r  )*20 + 2*tk];
        float2 v1 = *(const float2*)&Abase[(r+8)*20 + 2*tk];
        float2 v2 = *(const float2*)&Abase[(r  )*20 + 2*tk+8];
        float2 v3 = *(const float2*)&Abase[(r+8)*20 + 2*tk+8];
        a[i][0] = packh2(v0); a[i][1] = packh2(v1);
        a[i][2] = packh2(v2); a[i][3] = packh2(v3);
      }
    }
    #pragma unroll
    for (int j=0;j<8;j++){
      int c = warpN + j*8 + tg;
      b[j][0] = *(const uint32_t*)&Bbase[c*24 + 2*tk];
      b[j][1] = *(const uint32_t*)&Bbase[c*24 + 2*tk + 8];
    }
    #pragma unroll
    for (int i=0;i<2;i++)
      #pragma unroll
      for (int j=0;j<8;j++)
        asm volatile("mma.sync.aligned.m16n8k16.row.col.f32.f16.f16.f32 "
          "{%0,%1,%2,%3}, {%4,%5,%6,%7}, {%8,%9}, {%0,%1,%2,%3};"
          : "+f"(acc[i][j][0]), "+f"(acc[i][j][1]),
            "+f"(acc[i][j][2]), "+f"(acc[i][j][3])
          : "r"(a[i][0]), "r"(a[i][1]), "r"(a[i][2]), "r"(a[i][3]),
            "r"(b[j][0]), "r"(b[j][1]));
    st++; if (st>=3) st-=3;
  }

  // ---- epilogue ----
  const float BNS = rsqrtf(1.0f + 1e-5f);
  float mean=0.f, rdenom=1.f;
  if (EPI==EPI_RES){
    const float inv = 1.0f/((float)NN*(float)HD);
    mean = stats[0]*inv;
    float var = stats[1]*inv - mean*mean;
    rdenom = 1.f/(sqrtf(fmaxf(var,0.f)) + 1e-5f);
  }
  float ssum=0.f, sq=0.f;
  float pgate[2][2];
  if (EPI==EPI_POOL){
    pgate[0][0]=pgate[0][1]=pgate[1][0]=pgate[1][1]=0.f;
  }
  #pragma unroll
  for (int j=0;j<8;j++){
    int col = n0 + warpN + j*8 + tk*2;
    float b0 = biasp[col], b1 = biasp[col+1];
    float g0=0.f,g1=0.f,e0=0.f,e1=0.f;
    if (EPI==EPI_RELU_BN || EPI==EPI_GIN){
      g0=g[col]*BNS; g1=g[col+1]*BNS; e0=be[col]; e1=be[col+1];
    }
    float lg0=0.f,lg1=0.f,lb0=0.f,lb1=0.f;
    if (EPI==EPI_RES){
      lg0=lng[col]; lg1=lng[col+1]; lb0=lnb[col]; lb1=lnb[col+1];
    }
    float w20=0.f,w21=0.f;
    if (EPI==EPI_POOL){ w20=W2pool[col]; w21=W2pool[col+1]; }
    #pragma unroll
    for (int i=0;i<2;i++){
      #pragma unroll
      for (int h=0;h<2;h++){
        int row = m0 + warpM + i*16 + tg + h*8;
        float v0 = acc[i][j][h*2+0] + b0;
        float v1 = acc[i][j][h*2+1] + b1;
        if (EPI==EPI_RELU_BN){
          v0 = fmaxf(v0,0.f)*g0 + e0;
          v1 = fmaxf(v1,0.f)*g1 + e1;
        } else if (EPI==EPI_GIN){
          v0 = fmaxf(v0,0.f)*g0 + e0; v0 = (v0>0.f)? v0 : 0.2f*v0;
          v1 = fmaxf(v1,0.f)*g1 + e1; v1 = (v1>0.f)? v1 : 0.2f*v1;
          ssum += v0+v1; sq += v0*v0+v1*v1;
        } else if (EPI==EPI_RES){
          float2 hv = *(const float2*)&hres[(long)row*HD + col];
          v0 += (hv.x-mean)*rdenom*lg0 + lb0;
          v1 += (hv.y-mean)*rdenom*lg1 + lb1;
          v0 = (v0>0.f)? v0 : 0.2f*v0;
          v1 = (v1>0.f)? v1 : 0.2f*v1;
        } else if (EPI==EPI_POOL){
          pgate[i][h] += tanhf(v0)*w20 + tanhf(v1)*w21;
        }
        if (EPI!=EPI_POOL)
          *(float2*)&Cp[(long)row*HD + col] = make_float2(v0,v1);
      }
    }
  }
  if (EPI==EPI_GIN){
    #pragma unroll
    for (int off=16; off>0; off>>=1){
      ssum += __shfl_xor_sync(0xffffffffu, ssum, off);
      sq   += __shfl_xor_sync(0xffffffffu, sq,   off);
    }
    if (lane==0){
      atomicAdd(&statsOut[0], ssum);
      atomicAdd(&statsOut[1], sq);
    }
  }
  if (EPI==EPI_POOL){
    #pragma unroll
    for (int i=0;i<2;i++)
      #pragma unroll
      for (int h=0;h<2;h++){
        float p = pgate[i][h];
        p += __shfl_xor_sync(0xffffffffu, p, 1);
        p += __shfl_xor_sync(0xffffffffu, p, 2);
        if (tk==0){
          int row = m0 + warpM + i*16 + tg + h*8;
          atomicAdd(&gatebuf[row], p);
        }
      }
  }
}

// ------- GATv2: 4 warps/node = (edge-half x feature-half), float4 lanes -------
__global__ __launch_bounds__(256)
void gat_kernel(const float4* __restrict__ xl4, const float4* __restrict__ xr4,
                const int* __restrict__ indptr, const int* __restrict__ col,
                const float* __restrict__ att, const float* __restrict__ gbias,
                float* __restrict__ hout){
  __shared__ float part[2][2][32][5];
  int warpid = threadIdx.x >> 5;
  int lane = threadIdx.x & 31;
  int nib = warpid >> 2;
  int sub = warpid & 3;
  int eHalf = sub >> 1;
  int fHalf = sub & 1;
  int w = blockIdx.x*2 + nib;
  int fbase = fHalf*32 + lane;
  const float4* at4 = (const float4*)att;
  float4 a  = at4[fbase];
  float4 xr = xr4[w*64 + fbase];
  float4 acc = make_float4(0,0,0,0);
  float s = 0.f;
  int p0 = indptr[w], p1 = indptr[w+1];
  int mid = p0 + ((p1-p0)+1)/2;
  int jb = eHalf ? mid : p0;
  int je = eHalf ? p1  : mid;
  int j = jb;
  for (; j+1 < je; j += 2){
    int ua = col[j], ub = col[j+1];
    float4 xa = xl4[ua*64 + fbase];
    float4 xb = xl4[ub*64 + fbase];
    float qa, qb, v;
    v = xa.x+xr.x; v = fmaxf(v, 0.2f*v); qa  = v*a.x;
    v = xa.y+xr.y; v = fmaxf(v, 0.2f*v); qa += v*a.y;
    v = xa.z+xr.z; v = fmaxf(v, 0.2f*v); qa += v*a.z;
    v = xa.w+xr.w; v = fmaxf(v, 0.2f*v); qa += v*a.w;
    v = xb.x+xr.x; v = fmaxf(v, 0.2f*v); qb  = v*a.x;
    v = xb.y+xr.y; v = fmaxf(v, 0.2f*v); qb += v*a.y;
    v = xb.z+xr.z; v = fmaxf(v, 0.2f*v); qb += v*a.z;
    v = xb.w+xr.w; v = fmaxf(v, 0.2f*v); qb += v*a.w;
    qa += __shfl_xor_sync(0xffffffffu,qa,1);
    qb += __shfl_xor_sync(0xffffffffu,qb,1);
    qa += __shfl_xor_sync(0xffffffffu,qa,2);
    qb += __shfl_xor_sync(0xffffffffu,qb,2);
    qa += __shfl_xor_sync(0xffffffffu,qa,4);
    qb += __shfl_xor_sync(0xffffffffu,qb,4);
    float ca = __expf(qa), cb = __expf(qb);
    s += ca;
    acc.x += ca*xa.x; acc.y += ca*xa.y; acc.z += ca*xa.z; acc.w += ca*xa.w;
    s += cb;
    acc.x += cb*xb.x; acc.y += cb*xb.y; acc.z += cb*xb.z; acc.w += cb*xb.w;
  }
  if (j < je){
    int u = col[j];
    float4 x = xl4[u*64 + fbase];
    float q, v;
    v = x.x+xr.x; v = fmaxf(v, 0.2f*v); q  = v*a.x;
    v = x.y+xr.y; v = fmaxf(v, 0.2f*v); q += v*a.y;
    v = x.z+xr.z; v = fmaxf(v, 0.2f*v); q += v*a.z;
    v = x.w+xr.w; v = fmaxf(v, 0.2f*v); q += v*a.w;
    q += __shfl_xor_sync(0xffffffffu,q,1);
    q += __shfl_xor_sync(0xffffffffu,q,2);
    q += __shfl_xor_sync(0xffffffffu,q,4);
    float c = __expf(q);
    s += c;
    acc.x += c*x.x; acc.y += c*x.y; acc.z += c*x.z; acc.w += c*x.w;
  }
  if (eHalf == 1){
    part[nib][fHalf][lane][0] = acc.x;
    part[nib][fHalf][lane][1] = acc.y;
    part[nib][fHalf][lane][2] = acc.z;
    part[nib][fHalf][lane][3] = acc.w;
    part[nib][fHalf][lane][4] = s;
  }
  __syncthreads();
  if (eHalf == 0){
    acc.x += part[nib][fHalf][lane][0];
    acc.y += part[nib][fHalf][lane][1];
    acc.z += part[nib][fHalf][lane][2];
    acc.w += part[nib][fHalf][lane][3];
    s     += part[nib][fHalf][lane][4];
    float r = 1.f/(s+1e-16f);
    float4 b = ((const float4*)gbias)[fbase];
    float4 o;
    o.x = acc.x*r + b.x; o.y = acc.y*r + b.y;
    o.z = acc.z*r + b.z; o.w = acc.w*r + b.w;
    ((float4*)hout)[w*64 + fbase] = o;
  }
}

// ---- GIN aggregation via GAT CSR (self-loop in list), 4 warps/node ----
__global__ __launch_bounds__(256)
void ginagg_kernel(const float4* __restrict__ h4, const int* __restrict__ indptr,
                   const int* __restrict__ col, float* __restrict__ tmp){
  __shared__ float part[2][2][32][4];
  int warpid = threadIdx.x >> 5;
  int lane = threadIdx.x & 31;
  int nib = warpid >> 2;
  int sub = warpid & 3;
  int eHalf = sub >> 1;
  int fHalf = sub & 1;
  int w = blockIdx.x*2 + nib;
  int fbase = fHalf*32 + lane;
  float4 acc = make_float4(0,0,0,0);
  int p0 = indptr[w], p1 = indptr[w+1];
  int mid = p0 + ((p1-p0)+1)/2;
  int jb = eHalf ? mid : p0;
  int je = eHalf ? p1  : mid;
  int j = jb;
  for (; j+3 < je; j += 4){
    int u0 = col[j], u1 = col[j+1], u2 = col[j+2], u3 = col[j+3];
    float4 x0 = h4[u0*64 + fbase];
    float4 x1 = h4[u1*64 + fbase];
    float4 x2 = h4[u2*64 + fbase];
    float4 x3 = h4[u3*64 + fbase];
    acc.x+=x0.x; acc.y+=x0.y; acc.z+=x0.z; acc.w+=x0.w;
    acc.x+=x1.x; acc.y+=x1.y; acc.z+=x1.z; acc.w+=x1.w;
    acc.x+=x2.x; acc.y+=x2.y; acc.z+=x2.z; acc.w+=x2.w;
    acc.x+=x3.x; acc.y+=x3.y; acc.z+=x3.z; acc.w+=x3.w;
  }
  for (; j < je; j++){
    int u = col[j];
    float4 x = h4[u*64 + fbase];
    acc.x+=x.x; acc.y+=x.y; acc.z+=x.z; acc.w+=x.w;
  }
  if (eHalf == 1){
    part[nib][fHalf][lane][0]=acc.x;
    part[nib][fHalf][lane][1]=acc.y;
    part[nib][fHalf][lane][2]=acc.z;
    part[nib][fHalf][lane][3]=acc.w;
  }
  __syncthreads();
  if (eHalf == 0){
    acc.x+=part[nib][fHalf][lane][0];
    acc.y+=part[nib][fHalf][lane][1];
    acc.z+=part[nib][fHalf][lane][2];
    acc.w+=part[nib][fHalf][lane][3];
    ((float4*)tmp)[w*64 + fbase] = acc;
  }
}

// ---- pooling: batch softmax, warp-segmented (batch is sorted) ----
__global__ void bsoftmax_kernel(float* __restrict__ gate, const int* __restrict__ batch,
                                const float* __restrict__ b2, float* __restrict__ gsum){
  __shared__ float smax[GG], ssum[GG];
  int t = threadIdx.x;  // 1024 threads
  int lane = t & 31, wid = t >> 5;
  if (t < GG){ smax[t] = -1e30f; ssum[t] = 0.f; }
  __syncthreads();
  float b2v = b2[0];
  for (int base = wid*32; base < NN; base += 1024){
    int v = base + lane;
    bool ok = v < NN;
    int b = ok ? batch[v] : -1;
    float gv = ok ? gate[v]+b2v : -1e30f;
    int b0 = __shfl_sync(0xffffffffu, b, 0);
    if (__all_sync(0xffffffffu, b==b0 || !ok)){
      float m = gv;
      m = fmaxf(m, __shfl_xor_sync(0xffffffffu, m, 16));
      m = fmaxf(m, __shfl_xor_sync(0xffffffffu, m, 8));
      m = fmaxf(m, __shfl_xor_sync(0xffffffffu, m, 4));
      m = fmaxf(m, __shfl_xor_sync(0xffffffffu, m, 2));
      m = fmaxf(m, __shfl_xor_sync(0xffffffffu, m, 1));
      if (lane==0) atomicMaxF(&smax[b0], m);
    } else if (ok){
      atomicMaxF(&smax[b], gv);
    }
  }
  __syncthreads();
  for (int base = wid*32; base < NN; base += 1024){
    int v = base + lane;
    bool ok = v < NN;
    int b = ok ? batch[v] : -1;
    float e = 0.f;
    if (ok){
      e = __expf(gate[v]+b2v - smax[b]);
      gate[v] = e;
    }
    int b0 = __shfl_sync(0xffffffffu, b, 0);
    if (__all_sync(0xffffffffu, b==b0 || !ok)){
      float sum = e;
      sum += __shfl_xor_sync(0xffffffffu, sum, 16);
      sum += __shfl_xor_sync(0xffffffffu, sum, 8);
      sum += __shfl_xor_sync(0xffffffffu, sum, 4);
      sum += __shfl_xor_sync(0xffffffffu, sum, 2);
      sum += __shfl_xor_sync(0xffffffffu, sum, 1);
      if (lane==0) atomicAdd(&ssum[b0], sum);
    } else if (ok){
      atomicAdd(&ssum[b], e);
    }
  }
  __syncthreads();
  if (t < GG) gsum[t] = ssum[t];
}

__global__ __launch_bounds__(256)
void emb_kernel(const float* __restrict__ gate, const int* __restrict__ batch,
                const float* __restrict__ gsum, const float* __restrict__ h, float* __restrict__ emb){
  int w = (blockIdx.x*blockDim.x + threadIdx.x)>>5;
  int lane = threadIdx.x & 31;
  if (w >= NN) return;
  int b = batch[w];
  float c = gate[w]/(gsum[b]+1e-16f);
  #pragma unroll
  for (int k=0;k<8;k++) atomicAdd(&emb[b*HD + k*32 + lane], c*h[w*HD + k*32 + lane]);
}

// ---------------- label heads: grid (OO,2), 128 thr, hidden-split ----------------
__global__ __launch_bounds__(128)
void head_kernel(const float* __restrict__ emb, const float* __restrict__ W1,
                 const float* __restrict__ b1, const float* __restrict__ g,
                 const float* __restrict__ be, const float* __restrict__ W2,
                 float* __restrict__ out){
  __shared__ float embS[GG*HD];
  __shared__ float sred[GG];
  int o = blockIdx.x;
  int half = blockIdx.y;
  int t = threadIdx.x;
  int hu = half*128 + t;
  for (int i=t;i<GG*HD;i+=128) embS[i]=emb[i];
  if (t < GG) sred[t]=0.f;
  __syncthreads();
  float acc[GG];
  #pragma unroll
  for (int b=0;b<GG;b++) acc[b]=0.f;
  const float* w = W1 + (long)o*HD*256 + hu;
  for (int d=0;d<HD;d++){
    float wv = w[(long)d*256];
    #pragma unroll
    for (int b=0;b<GG;b++) acc[b] += embS[b*HD+d]*wv;
  }
  const float BNS = rsqrtf(1.0f + 1e-5f);
  float bnscale = g[o*256+hu]*BNS;
  float beta = be[o*256+hu];
  float bb1 = b1[o*256+hu];
  float w2 = W2[o*256+hu];
  #pragma unroll
  for (int b=0;b<GG;b++){
    float z = acc[b]+bb1;
    float sv = z/(1.f+__expf(-z));
    float bnv = sv*bnscale + beta;
    atomicAdd(&sred[b], bnv*w2);
  }
  __syncthreads();
  if (t < GG) atomicAdd(&out[t*OO + o], sred[t]);
}

// ---------------- host launch ----------------
extern "C" void kernel_launch(void* const* d_in, const int* in_sizes, int n_in,
                              void* d_out, int out_size) {
  (void)in_sizes; (void)n_in; (void)out_size;
  const float* x      = (const float*)d_in[0];
  const int*   ei     = (const int*)  d_in[1];
  const int*   batch  = (const int*)  d_in[2];
  const float* fp_W   = (const float*)d_in[3];
  const float* fp_b   = (const float*)d_in[4];
  const float* fp_g   = (const float*)d_in[5];
  const float* fp_be  = (const float*)d_in[6];
  const float* gat_Wl = (const float*)d_in[7];
  const float* gat_bl = (const float*)d_in[8];
  const float* gat_Wr = (const float*)d_in[9];
  const float* gat_br = (const float*)d_in[10];
  const float* gat_att= (const float*)d_in[11];
  const float* gat_bias=(const float*)d_in[12];
  const float* gin_W  = (const float*)d_in[13];
  const float* gin_b  = (const float*)d_in[14];
  const float* gin_g  = (const float*)d_in[15];
  const float* gin_be = (const float*)d_in[16];
  const float* ln_g   = (const float*)d_in[17];
  const float* ln_b   = (const float*)d_in[18];
  const float* res_W  = (const float*)d_in[19];
  const float* res_b  = (const float*)d_in[20];
  const float* pool_W1= (const float*)d_in[21];
  const float* pool_b1= (const float*)d_in[22];
  const float* pool_W2= (const float*)d_in[23];
  const float* pool_b2= (const float*)d_in[24];
  const float* head_W1= (const float*)d_in[25];
  const float* head_b1= (const float*)d_in[26];
  const float* head_g = (const float*)d_in[27];
  const float* head_be= (const float*)d_in[28];
  const float* head_W2= (const float*)d_in[29];
  const float* head_b2= (const float*)d_in[30];

  float *h0,*h1,*xl,*xr,*red,*gate,*gsum,*emb;
  __half *rw, *xh;
  int *degGat,*ptrGat,*curGat,*colGat;
  cudaGetSymbolAddress((void**)&h0, d_h0);
  cudaGetSymbolAddress((void**)&h1, d_h1);
  cudaGetSymbolAddress((void**)&xl, d_xl);
  cudaGetSymbolAddress((void**)&xr, d_xr);
  cudaGetSymbolAddress((void**)&xh, d_xh);
  cudaGetSymbolAddress((void**)&rw, d_rw);
  cudaGetSymbolAddress((void**)&red, d_red);
  cudaGetSymbolAddress((void**)&gate, d_gate);
  cudaGetSymbolAddress((void**)&gsum, d_gsum);
  cudaGetSymbolAddress((void**)&emb, d_emb);
  cudaGetSymbolAddress((void**)&degGat, d_degGat);
  cudaGetSymbolAddress((void**)&ptrGat, d_ptrGat);
  cudaGetSymbolAddress((void**)&curGat, d_curGat);
  cudaGetSymbolAddress((void**)&colGat, d_colGat);

  cudaFuncSetAttribute(gemm_tc<EPI_RELU_BN,false,true>, cudaFuncAttributeMaxDynamicSharedMemorySize, SMEM_SZ);
  cudaFuncSetAttribute(gemm_tc<EPI_BIAS,true,false>,    cudaFuncAttributeMaxDynamicSharedMemorySize, SMEM_SZ);
  cudaFuncSetAttribute(gemm_tc<EPI_GIN,false,false>,    cudaFuncAttributeMaxDynamicSharedMemorySize, SMEM_SZ);
  cudaFuncSetAttribute(gemm_tc<EPI_RES,false,false>,    cudaFuncAttributeMaxDynamicSharedMemorySize, SMEM_SZ);
  cudaFuncSetAttribute(gemm_tc<EPI_POOL,false,false>,   cudaFuncAttributeMaxDynamicSharedMemorySize, SMEM_SZ);

  dim3 gg1(NN/128, 2);   // (125,2): two N-halves
  dim3 gg2(NN/128, 4);   // dual: y = wset*2 + nhalf

  // launch 1: init + x->f16 + weight repack + hist + scan
  csr_kernel<<<CSR_BLOCKS, 1024>>>(ei, x, degGat, ptrGat, curGat,
                                   red, emb, gate, (float*)d_out, head_b2,
                                   fp_W, gat_Wl, gat_Wr, gin_W, res_W, pool_W1, xh, rw);
  // launch 2: CSR fill
  fill_kernel<<<(EP+255)/256, 256>>>(ei, curGat, colGat);
  // launch 3: feature projection (A pre-rounded f16)
  gemm_tc<EPI_RELU_BN,false,true><<<gg1,256,SMEM_SZ>>>(xh, rw+FPW_OFF, fp_b, nullptr,nullptr,nullptr,
      fp_g, fp_be, nullptr,nullptr,nullptr,nullptr,nullptr,nullptr,nullptr, h0, DIN);

  float* cur = h0;
  float* alt = h1;
  for (int i=0;i<2;i++){
    const __half* Wl = rw + WL_OFF + (long)i*HD*HD;
    const float*  bl = gat_bl + (long)i*HD;
    const __half* Wr = rw + WR_OFF + (long)i*HD*HD;
    const float*  br = gat_br + (long)i*HD;
    const float*  at = gat_att + (long)i*8*32;
    const float*  gb = gat_bias + (long)i*HD;
    const __half* gW = rw + GINW_OFF + (long)i*HD*HD;
    const float*  gbi= gin_b + (long)i*HD;
    const float*  ggm= gin_g + (long)i*HD;
    const float*  gbe= gin_be + (long)i*HD;
    const float*  lg = ln_g + (long)i*HD;
    const float*  lb = ln_b + (long)i*HD;
    const __half* rW = rw + RESW_OFF + (long)i*HD*HD;
    const float*  rb = res_b + (long)i*HD;

    // launch 4 (i=0): dual GEMM  <-- ncu capture target
    gemm_tc<EPI_BIAS,true,false><<<gg2,256,SMEM_SZ>>>(cur, Wl, bl, Wr, br, xr,
        nullptr,nullptr,nullptr,nullptr,nullptr,nullptr,nullptr,nullptr,nullptr, xl, HD);
    gat_kernel<<<NN/2, 256>>>((const float4*)xl, (const float4*)xr, ptrGat, colGat, at, gb, alt);
    { float* t = cur; cur = alt; alt = t; }

    ginagg_kernel<<<NN/2, 256>>>((const float4*)cur, ptrGat, colGat, xl);
    gemm_tc<EPI_GIN,false,false><<<gg1,256,SMEM_SZ>>>(xl, gW, gbi, nullptr,nullptr,nullptr,
        ggm, gbe, nullptr,nullptr,nullptr,nullptr, red + 2*i, nullptr,nullptr, alt, HD);
    { float* t = cur; cur = alt; alt = t; }

    gemm_tc<EPI_RES,false,false><<<gg1,256,SMEM_SZ>>>(cur, rW, rb, nullptr,nullptr,nullptr,
        nullptr,nullptr, lg, lb, cur, red + 2*i, nullptr,nullptr,nullptr, alt, HD);
    { float* t = cur; cur = alt; alt = t; }
  }

  gemm_tc<EPI_POOL,false,false><<<gg1,256,SMEM_SZ>>>(cur, rw+POOLW_OFF, pool_b1, nullptr,nullptr,nullptr,
      nullptr,nullptr,nullptr,nullptr,nullptr,nullptr,nullptr, pool_W2, gate, nullptr, HD);
  bsoftmax_kernel<<<1, 1024>>>(gate, batch, pool_b2, gsum);
  emb_kernel<<<NN/8, 256>>>(gate, batch, gsum, cur, emb);

  head_kernel<<<dim3(OO,2), 128>>>(emb, head_W1, head_b1, head_g, head_be, head_W2, (float*)d_out);
}